// round 2
// baseline (speedup 1.0000x reference)
#include <cuda_runtime.h>
#include <math.h>

#define BB 4
#define SS 2048
#define DD 1024
#define HH 16
#define AA 64

#define MQ 128     // q rows per attention block
#define NK 64      // k cols per tile
#define KST 68     // KsT row stride (floats), 272B = 16B-aligned, conflict-padded
#define PST 68     // Ps row stride

// ---- scratch: projected q/k/v heads, layout [b][h][s][a] ----
__device__ float g_qh[BB*HH*SS*AA];
__device__ float g_kh[BB*HH*SS*AA];
__device__ float g_vh[BB*HH*SS*AA];

// FFMA-only exp (avoids MUFU.EX2 throughput wall). Valid for x <= 0 (and -inf).
__device__ __forceinline__ float fast_exp(float x) {
    float t = x * 1.4426950408889634f;       // x * log2(e)
    t = fmaxf(t, -125.0f);                   // handles -inf, avoids denormal exponent
    int ii = __float2int_rn(t);
    float f = t - (float)ii;                 // f in [-0.5, 0.5]
    float p =              1.5252733e-5f;
    p = fmaf(p, f, 1.5403530e-4f);
    p = fmaf(p, f, 1.3333558e-3f);
    p = fmaf(p, f, 9.6181291e-3f);
    p = fmaf(p, f, 5.5504109e-2f);
    p = fmaf(p, f, 2.4022651e-1f);
    p = fmaf(p, f, 6.9314718e-1f);
    p = fmaf(p, f, 1.0f);
    return p * __int_as_float((ii + 127) << 23);   // * 2^ii
}

// ======================= projection: out[b,h,s,a] = sum_d X[b,s,d] W[h,d,a] + bias[h,a]
// grid (64, 16) = (row-tiles of 128 over B*S, heads). 256 threads. tile 128x64, K-chunk 32.
// which: 0 -> g_qh, 1 -> g_kh, 2 -> g_vh  (avoids any host-side symbol lookup)
__global__ __launch_bounds__(256) void proj_kernel(
    const float* __restrict__ X, const float* __restrict__ W,
    const float* __restrict__ bias, int which)
{
    float* __restrict__ out = (which == 0) ? g_qh : (which == 1) ? g_kh : g_vh;
    __shared__ float Xs[32][132];   // [k][m], padded
    __shared__ float Ws[32][64];    // [k][n]
    const int h  = blockIdx.y;
    const int r0 = blockIdx.x * 128;
    const int t  = threadIdx.x;
    const int tx = t & 15, ty = t >> 4;
    const int m0 = ty * 8, n0 = tx * 4;
    const float* Wh = W + (size_t)h * DD * AA;

    float acc[8][4];
    #pragma unroll
    for (int i = 0; i < 8; i++)
        #pragma unroll
        for (int j = 0; j < 4; j++) acc[i][j] = 0.0f;

    for (int k0 = 0; k0 < DD; k0 += 32) {
        // load X tile transposed: 128 rows x 32 k
        #pragma unroll
        for (int i = 0; i < 4; i++) {
            int f = t + i * 256;          // 0..1023 float4s
            int m = f >> 3, jq = f & 7;
            float4 x4 = *(const float4*)(X + (size_t)(r0 + m) * DD + k0 + jq * 4);
            Xs[jq*4+0][m] = x4.x; Xs[jq*4+1][m] = x4.y;
            Xs[jq*4+2][m] = x4.z; Xs[jq*4+3][m] = x4.w;
        }
        // load W tile: 32 k x 64 n
        #pragma unroll
        for (int i = 0; i < 2; i++) {
            int f = t + i * 256;          // 0..511 float4s
            int kk = f >> 4, nq = f & 15;
            *(float4*)&Ws[kk][nq*4] = *(const float4*)(Wh + (size_t)(k0 + kk) * AA + nq * 4);
        }
        __syncthreads();
        #pragma unroll
        for (int kk = 0; kk < 32; kk++) {
            float4 xa = *(const float4*)&Xs[kk][m0];
            float4 xb = *(const float4*)&Xs[kk][m0 + 4];
            float4 wv = *(const float4*)&Ws[kk][n0];
            float xs[8] = {xa.x, xa.y, xa.z, xa.w, xb.x, xb.y, xb.z, xb.w};
            float ws[4] = {wv.x, wv.y, wv.z, wv.w};
            #pragma unroll
            for (int i = 0; i < 8; i++)
                #pragma unroll
                for (int j = 0; j < 4; j++)
                    acc[i][j] = fmaf(xs[i], ws[j], acc[i][j]);
        }
        __syncthreads();
    }
    float4 bb = *(const float4*)(bias + h * AA + n0);
    float bs[4] = {bb.x, bb.y, bb.z, bb.w};
    #pragma unroll
    for (int i = 0; i < 8; i++) {
        int r = r0 + m0 + i;
        int b = r >> 11, s = r & (SS - 1);
        float4 o;
        o.x = acc[i][0] + bs[0]; o.y = acc[i][1] + bs[1];
        o.z = acc[i][2] + bs[2]; o.w = acc[i][3] + bs[3];
        *(float4*)(out + ((size_t)((b * HH + h) * SS + s)) * AA + n0) = o;
    }
}

// ======================= flash attention (fp32, no scaling, no mask)
// grid (S/128, B*H). 256 threads. per-thread 8x4 register tiles for S and O.
__global__ __launch_bounds__(256) void attn_kernel(float* __restrict__ out)
{
    extern __shared__ float sm[];
    float* Qs  = sm;                      // 128*64
    float* KsT = Qs  + MQ * AA;           // 64*KST   [a][c]
    float* Vs  = KsT + AA * KST;          // 64*64    [c][a]
    float* Ps  = Vs  + NK * AA;           // 128*PST  [r][c]

    const int bh = blockIdx.y;
    const int q0 = blockIdx.x * MQ;
    const float* Qbh = g_qh + ((size_t)bh * SS + q0) * AA;
    const float* Kbh = g_kh + (size_t)bh * SS * AA;
    const float* Vbh = g_vh + (size_t)bh * SS * AA;
    const int t  = threadIdx.x;
    const int tx = t & 15, ty = t >> 4;
    const int m0 = ty * 8, c0 = tx * 4;   // c0 doubles as a0 in PV/output

    // load Q tile once
    #pragma unroll
    for (int i = 0; i < 8; i++) {
        int f = t + i * 256;
        ((float4*)Qs)[f] = ((const float4*)Qbh)[f];
    }

    float O[8][4];
    float mi[8], li[8];
    #pragma unroll
    for (int i = 0; i < 8; i++) {
        mi[i] = -INFINITY; li[i] = 0.0f;
        #pragma unroll
        for (int j = 0; j < 4; j++) O[i][j] = 0.0f;
    }

    for (int kt = 0; kt < SS; kt += NK) {
        __syncthreads();   // prior tile's smem reads complete
        // fill KsT transposed (STS conflict-free mapping)
        #pragma unroll
        for (int i = 0; i < 4; i++) {
            int f = t + i * 256;          // 0..1023
            int c = f & 63, aq = f >> 6;
            float4 k4 = *(const float4*)(Kbh + (size_t)(kt + c) * AA + aq * 4);
            KsT[(aq*4+0)*KST + c] = k4.x;
            KsT[(aq*4+1)*KST + c] = k4.y;
            KsT[(aq*4+2)*KST + c] = k4.z;
            KsT[(aq*4+3)*KST + c] = k4.w;
        }
        // fill Vs (natural layout, coalesced)
        #pragma unroll
        for (int i = 0; i < 4; i++) {
            int f = t + i * 256;
            int c = f >> 4, aq = f & 15;
            ((float4*)Vs)[f] = *(const float4*)(Vbh + (size_t)(kt + c) * AA + aq * 4);
        }
        __syncthreads();

        // ---- S = Q * K^T  (tile 128x64, inner A=64)
        float sacc[8][4];
        #pragma unroll
        for (int i = 0; i < 8; i++)
            #pragma unroll
            for (int j = 0; j < 4; j++) sacc[i][j] = 0.0f;

        #pragma unroll
        for (int a4 = 0; a4 < AA; a4 += 4) {
            float4 k0v = *(const float4*)&KsT[(a4+0)*KST + c0];
            float4 k1v = *(const float4*)&KsT[(a4+1)*KST + c0];
            float4 k2v = *(const float4*)&KsT[(a4+2)*KST + c0];
            float4 k3v = *(const float4*)&KsT[(a4+3)*KST + c0];
            #pragma unroll
            for (int i = 0; i < 8; i++) {
                float4 qv = *(const float4*)&Qs[(m0 + i) * AA + a4];
                sacc[i][0] = fmaf(qv.x,k0v.x,fmaf(qv.y,k1v.x,fmaf(qv.z,k2v.x,fmaf(qv.w,k3v.x,sacc[i][0]))));
                sacc[i][1] = fmaf(qv.x,k0v.y,fmaf(qv.y,k1v.y,fmaf(qv.z,k2v.y,fmaf(qv.w,k3v.y,sacc[i][1]))));
                sacc[i][2] = fmaf(qv.x,k0v.z,fmaf(qv.y,k1v.z,fmaf(qv.z,k2v.z,fmaf(qv.w,k3v.z,sacc[i][2]))));
                sacc[i][3] = fmaf(qv.x,k0v.w,fmaf(qv.y,k1v.w,fmaf(qv.z,k2v.w,fmaf(qv.w,k3v.w,sacc[i][3]))));
            }
        }

        // ---- online softmax update (16 lanes of a row-group reduce via shfl)
        #pragma unroll
        for (int i = 0; i < 8; i++) {
            float tm = fmaxf(fmaxf(sacc[i][0], sacc[i][1]), fmaxf(sacc[i][2], sacc[i][3]));
            tm = fmaxf(tm, __shfl_xor_sync(0xffffffffu, tm, 1));
            tm = fmaxf(tm, __shfl_xor_sync(0xffffffffu, tm, 2));
            tm = fmaxf(tm, __shfl_xor_sync(0xffffffffu, tm, 4));
            tm = fmaxf(tm, __shfl_xor_sync(0xffffffffu, tm, 8));
            float mnew = fmaxf(mi[i], tm);
            float corr = fast_exp(mi[i] - mnew);
            mi[i] = mnew;
            float p0 = fast_exp(sacc[i][0] - mnew);
            float p1 = fast_exp(sacc[i][1] - mnew);
            float p2 = fast_exp(sacc[i][2] - mnew);
            float p3 = fast_exp(sacc[i][3] - mnew);
            float rs = (p0 + p1) + (p2 + p3);
            rs += __shfl_xor_sync(0xffffffffu, rs, 1);
            rs += __shfl_xor_sync(0xffffffffu, rs, 2);
            rs += __shfl_xor_sync(0xffffffffu, rs, 4);
            rs += __shfl_xor_sync(0xffffffffu, rs, 8);
            li[i] = fmaf(li[i], corr, rs);
            O[i][0] *= corr; O[i][1] *= corr; O[i][2] *= corr; O[i][3] *= corr;
            *(float4*)&Ps[(m0 + i) * PST + c0] = make_float4(p0, p1, p2, p3);
        }
        __syncthreads();   // Ps visible

        // ---- O += P * V  (inner NK=64)
        #pragma unroll
        for (int c4 = 0; c4 < NK; c4 += 4) {
            float4 v0 = *(const float4*)&Vs[(c4+0)*AA + c0];
            float4 v1 = *(const float4*)&Vs[(c4+1)*AA + c0];
            float4 v2 = *(const float4*)&Vs[(c4+2)*AA + c0];
            float4 v3 = *(const float4*)&Vs[(c4+3)*AA + c0];
            #pragma unroll
            for (int i = 0; i < 8; i++) {
                float4 pv = *(const float4*)&Ps[(m0 + i) * PST + c4];
                O[i][0] = fmaf(pv.x,v0.x,fmaf(pv.y,v1.x,fmaf(pv.z,v2.x,fmaf(pv.w,v3.x,O[i][0]))));
                O[i][1] = fmaf(pv.x,v0.y,fmaf(pv.y,v1.y,fmaf(pv.z,v2.y,fmaf(pv.w,v3.y,O[i][1]))));
                O[i][2] = fmaf(pv.x,v0.z,fmaf(pv.y,v1.z,fmaf(pv.z,v2.z,fmaf(pv.w,v3.z,O[i][2]))));
                O[i][3] = fmaf(pv.x,v0.w,fmaf(pv.y,v1.w,fmaf(pv.z,v2.w,fmaf(pv.w,v3.w,O[i][3]))));
            }
        }
    }

    // ---- epilogue: normalize, write [b, s, h*A + a]
    const int b = bh >> 4, h = bh & 15;
    #pragma unroll
    for (int i = 0; i < 8; i++) {
        float inv = 1.0f / li[i];
        size_t off = ((size_t)(b * SS + q0 + m0 + i)) * (HH * AA) + h * AA + c0;
        *(float4*)(out + off) = make_float4(O[i][0]*inv, O[i][1]*inv, O[i][2]*inv, O[i][3]*inv);
    }
}

static const int ATTN_SMEM = (MQ*AA + AA*KST + NK*AA + MQ*PST) * (int)sizeof(float); // 101376 B

extern "C" void kernel_launch(void* const* d_in, const int* in_sizes, int n_in,
                              void* d_out, int out_size) {
    (void)in_sizes; (void)n_in; (void)out_size;
    const float* q  = (const float*)d_in[0];
    const float* k  = (const float*)d_in[1];
    const float* v  = (const float*)d_in[2];
    const float* Wq = (const float*)d_in[3];
    const float* bq = (const float*)d_in[4];
    const float* Wk = (const float*)d_in[5];
    const float* bk = (const float*)d_in[6];
    const float* Wv = (const float*)d_in[7];
    const float* bv = (const float*)d_in[8];
    float* out = (float*)d_out;

    dim3 pg(BB * SS / 128, HH);
    proj_kernel<<<pg, 256>>>(q, Wq, bq, 0);
    proj_kernel<<<pg, 256>>>(k, Wk, bk, 1);
    proj_kernel<<<pg, 256>>>(v, Wv, bv, 2);

    cudaFuncSetAttribute(attn_kernel, cudaFuncAttributeMaxDynamicSharedMemorySize, ATTN_SMEM);
    dim3 ag(SS / MQ, BB * HH);
    attn_kernel<<<ag, 256, ATTN_SMEM>>>(out);
}

// round 4
// speedup vs baseline: 2.1663x; 2.1663x over previous
#include <cuda_runtime.h>
#include <cuda_bf16.h>
#include <math.h>
#include <stdint.h>

#define BB 4
#define SS 2048
#define DD 1024
#define HH 16
#define AA 64
#define NN (HH*AA)   // 1024

typedef __nv_bfloat16 bf16;
typedef __nv_bfloat162 bf162;

// ---- scratch: projected heads as bf16 hi/lo pairs, layout [b*H+h][s][a] ----
__device__ bf16 g_qhi[BB*HH*SS*AA];
__device__ bf16 g_qlo[BB*HH*SS*AA];
__device__ bf16 g_khi[BB*HH*SS*AA];
__device__ bf16 g_klo[BB*HH*SS*AA];
__device__ bf16 g_vhi[BB*HH*SS*AA];
__device__ bf16 g_vlo[BB*HH*SS*AA];
// inputs split
__device__ bf16 g_xhi[BB*SS*DD];
__device__ bf16 g_xlo[BB*SS*DD];
__device__ bf16 g_whi[NN*DD];
__device__ bf16 g_wlo[NN*DD];

// ======================= helpers =======================
__device__ __forceinline__ uint32_t smem_u32(const void* p) {
    uint32_t a;
    asm("{ .reg .u64 t; cvta.to.shared.u64 t, %1; cvt.u32.u64 %0, t; }" : "=r"(a) : "l"(p));
    return a;
}
__device__ __forceinline__ void mma16816(float* c, const uint32_t* a, const uint32_t* b) {
    asm volatile(
        "mma.sync.aligned.m16n8k16.row.col.f32.bf16.bf16.f32 "
        "{%0,%1,%2,%3}, {%4,%5,%6,%7}, {%8,%9}, {%0,%1,%2,%3};"
        : "+f"(c[0]), "+f"(c[1]), "+f"(c[2]), "+f"(c[3])
        : "r"(a[0]), "r"(a[1]), "r"(a[2]), "r"(a[3]), "r"(b[0]), "r"(b[1]));
}
__device__ __forceinline__ void ldsm4(uint32_t* r, uint32_t addr) {
    asm volatile("ldmatrix.sync.aligned.m8n8.x4.shared.b16 {%0,%1,%2,%3}, [%4];"
        : "=r"(r[0]), "=r"(r[1]), "=r"(r[2]), "=r"(r[3]) : "r"(addr));
}
__device__ __forceinline__ void ldsm4t(uint32_t* r, uint32_t addr) {
    asm volatile("ldmatrix.sync.aligned.m8n8.x4.trans.shared.b16 {%0,%1,%2,%3}, [%4];"
        : "=r"(r[0]), "=r"(r[1]), "=r"(r[2]), "=r"(r[3]) : "r"(addr));
}
__device__ __forceinline__ void split2(float p0, float p1, uint32_t& hi, uint32_t& lo) {
    bf162 h = __floats2bfloat162_rn(p0, p1);   // x = p0 (low half), y = p1
    bf162 l = __floats2bfloat162_rn(p0 - __bfloat162float(h.x), p1 - __bfloat162float(h.y));
    hi = *reinterpret_cast<uint32_t*>(&h);
    lo = *reinterpret_cast<uint32_t*>(&l);
}
// FFMA-only exp; valid for x <= 0 (and -inf)
__device__ __forceinline__ float fast_exp(float x) {
    float t = x * 1.4426950408889634f;
    t = fmaxf(t, -125.0f);
    int ii = __float2int_rn(t);
    float f = t - (float)ii;
    float p =              1.5252733e-5f;
    p = fmaf(p, f, 1.5403530e-4f);
    p = fmaf(p, f, 1.3333558e-3f);
    p = fmaf(p, f, 9.6181291e-3f);
    p = fmaf(p, f, 5.5504109e-2f);
    p = fmaf(p, f, 2.4022651e-1f);
    p = fmaf(p, f, 6.9314718e-1f);
    p = fmaf(p, f, 1.0f);
    return p * __int_as_float((ii + 127) << 23);
}

// ======================= conversion kernels =======================
__global__ __launch_bounds__(256) void cvt_x(const float* __restrict__ X) {
    int i = blockIdx.x * 256 + threadIdx.x;   // float4 index, total 2M
    float4 x = ((const float4*)X)[i];
    bf16 h0 = __float2bfloat16(x.x), h1 = __float2bfloat16(x.y);
    bf16 h2 = __float2bfloat16(x.z), h3 = __float2bfloat16(x.w);
    bf16 l0 = __float2bfloat16(x.x - __bfloat162float(h0));
    bf16 l1 = __float2bfloat16(x.y - __bfloat162float(h1));
    bf16 l2 = __float2bfloat16(x.z - __bfloat162float(h2));
    bf16 l3 = __float2bfloat16(x.w - __bfloat162float(h3));
    bf162* ph = (bf162*)g_xhi;
    bf162* pl = (bf162*)g_xlo;
    ph[2*i]   = __halves2bfloat162(h0, h1);
    ph[2*i+1] = __halves2bfloat162(h2, h3);
    pl[2*i]   = __halves2bfloat162(l0, l1);
    pl[2*i+1] = __halves2bfloat162(l2, l3);
}
// W [H, D, A] f32 -> Wt hi/lo bf16 [n=H*A][k=D]
__global__ __launch_bounds__(256) void cvt_w(const float* __restrict__ W) {
    int idx = blockIdx.x * 256 + threadIdx.x;  // float4 over [H,D,A]
    float4 wv = ((const float4*)W)[idx];
    int a4 = idx & 15;
    int d  = (idx >> 4) & 1023;
    int h  = idx >> 14;
    int nb = h * AA + a4 * 4;
    float vals[4] = {wv.x, wv.y, wv.z, wv.w};
    #pragma unroll
    for (int j = 0; j < 4; j++) {
        bf16 hi = __float2bfloat16(vals[j]);
        bf16 lo = __float2bfloat16(vals[j] - __bfloat162float(hi));
        size_t o = (size_t)(nb + j) * DD + d;
        g_whi[o] = hi;
        g_wlo[o] = lo;
    }
}

// ======================= projection GEMM (mma.sync, bf16-split) =======================
// C[8192,1024] = Xsplit * Wsplit^T + bias.  Tile 128x128, 256 thr, warps 2(m) x 4(n),
// warp tile 64x32. K chunks of 32, double-buffered smem with register prefetch.
#define KC 32
#define XP 40                                  // padded stride (halves): 80B rows
#define STG (4*128*XP)                         // halves per stage (Xhi,Xlo,Whi,Wlo)
#define PROJ_SMEM (2*STG*2)                    // bytes = 81920

__global__ __launch_bounds__(256) void proj_mma(const float* __restrict__ bias, int which) {
    bf16 *outhi, *outlo;
    if      (which == 0) { outhi = g_qhi; outlo = g_qlo; }
    else if (which == 1) { outhi = g_khi; outlo = g_klo; }
    else                 { outhi = g_vhi; outlo = g_vlo; }
    extern __shared__ bf16 sm[];
    const int t = threadIdx.x, lane = t & 31, wid = t >> 5;
    const int wm = wid & 1, wn = wid >> 1;
    const int r0 = blockIdx.x * 128, n0 = blockIdx.y * 128;
    const uint32_t sbase = smem_u32(sm);

    float c[4][4][4];
    #pragma unroll
    for (int mt = 0; mt < 4; mt++)
        #pragma unroll
        for (int nt = 0; nt < 4; nt++)
            #pragma unroll
            for (int i = 0; i < 4; i++) c[mt][nt][i] = 0.0f;

    uint4 pf[8];
    // arr = i>>1: 0 Xhi, 1 Xlo, 2 Whi, 3 Wlo;  rem = (i&1)*256 + t; row = rem>>2; cq = rem&3
#define PF_LOAD(kc_) do {                                                       \
    int k0_ = (kc_) * KC;                                                       \
    _Pragma("unroll")                                                           \
    for (int i = 0; i < 8; i++) {                                               \
        int rem = ((i & 1) << 8) + t; int row = rem >> 2, cq = rem & 3;         \
        const bf16* src;                                                        \
        if      ((i >> 1) == 0) src = g_xhi + (size_t)(r0 + row) * DD + k0_ + cq * 8; \
        else if ((i >> 1) == 1) src = g_xlo + (size_t)(r0 + row) * DD + k0_ + cq * 8; \
        else if ((i >> 1) == 2) src = g_whi + (size_t)(n0 + row) * DD + k0_ + cq * 8; \
        else                    src = g_wlo + (size_t)(n0 + row) * DD + k0_ + cq * 8; \
        pf[i] = *(const uint4*)src;                                             \
    } } while (0)
#define PF_STORE(buf_) do {                                                     \
    _Pragma("unroll")                                                           \
    for (int i = 0; i < 8; i++) {                                               \
        int rem = ((i & 1) << 8) + t; int row = rem >> 2, cq = rem & 3;         \
        bf16* dst = sm + (buf_) * STG + (i >> 1) * (128 * XP) + row * XP + cq * 8; \
        *(uint4*)dst = pf[i];                                                   \
    } } while (0)

    PF_LOAD(0);
    #pragma unroll 1
    for (int kc = 0; kc < DD / KC; kc++) {
        const int buf = kc & 1;
        PF_STORE(buf);
        __syncthreads();
        if (kc + 1 < DD / KC) PF_LOAD(kc + 1);

        const uint32_t stage = sbase + buf * (STG * 2);     // bytes
        #pragma unroll
        for (int ka = 0; ka < 2; ka++) {
            const int kk = ka * 16;
            uint32_t xh[4][4], xl[4][4];
            #pragma unroll
            for (int mt = 0; mt < 4; mt++) {
                uint32_t addr = stage +
                    ((wm * 64 + mt * 16 + (lane & 15)) * XP + kk + (lane >> 4) * 8) * 2;
                ldsm4(xh[mt], addr);
                ldsm4(xl[mt], addr + 128 * XP * 2);
            }
            #pragma unroll
            for (int np = 0; np < 2; np++) {
                uint32_t wh[4], wl[4];
                int brow = wn * 32 + np * 16 + (lane & 7) + ((lane & 16) ? 8 : 0);
                uint32_t baddr = stage + (2 * 128 * XP) * 2 +
                    (brow * XP + kk + ((lane >> 3) & 1) * 8) * 2;
                ldsm4(wh, baddr);
                ldsm4(wl, baddr + 128 * XP * 2);
                #pragma unroll
                for (int mt = 0; mt < 4; mt++) {
                    mma16816(c[mt][2*np],   xh[mt], &wh[0]);
                    mma16816(c[mt][2*np],   xh[mt], &wl[0]);
                    mma16816(c[mt][2*np],   xl[mt], &wh[0]);
                    mma16816(c[mt][2*np+1], xh[mt], &wh[2]);
                    mma16816(c[mt][2*np+1], xh[mt], &wl[2]);
                    mma16816(c[mt][2*np+1], xl[mt], &wh[2]);
                }
            }
        }
    }

    // epilogue: +bias, split to hi/lo bf16, store [b*H+h][s][a]
    const int g = lane >> 2, l = lane & 3;
    #pragma unroll
    for (int mt = 0; mt < 4; mt++) {
        int row = r0 + wm * 64 + mt * 16 + g;
        int b = row >> 11, s = row & (SS - 1);
        #pragma unroll
        for (int nt = 0; nt < 4; nt++) {
            int n = n0 + wn * 32 + nt * 8 + l * 2;
            int h = n >> 6, a = n & 63;
            size_t off = ((size_t)(b * HH + h) * SS + s) * AA + a;
            float bv0 = bias[n], bv1 = bias[n + 1];
            uint32_t hi, lo;
            split2(c[mt][nt][0] + bv0, c[mt][nt][1] + bv1, hi, lo);
            *(uint32_t*)(outhi + off) = hi;
            *(uint32_t*)(outlo + off) = lo;
            split2(c[mt][nt][2] + bv0, c[mt][nt][3] + bv1, hi, lo);
            *(uint32_t*)(outhi + off + 8 * AA) = hi;
            *(uint32_t*)(outlo + off + 8 * AA) = lo;
        }
    }
}

// ======================= flash attention (mma.sync, bf16-split) =======================
// grid (S/128, B*H), 256 thr. Warp w: rows w*16..w*16+15 of the 128-row q tile, all 64 keys.
#define QP 72                                  // padded stride halves (144B rows)
#define OFF_QL (128*QP*2)
#define OFF_KH (256*QP*2)
#define OFF_KL (OFF_KH + 64*QP*2)
#define OFF_VH (OFF_KH + 128*QP*2)
#define OFF_VL (OFF_KH + 192*QP*2)
#define ATTN_SMEM (OFF_KH + 256*QP*2)          // 73728 bytes

__global__ __launch_bounds__(256) void attn_mma(float* __restrict__ out) {
    extern __shared__ bf16 smh[];
    bf16* Qh = smh;
    bf16* Ql = Qh + 128 * QP;
    bf16* Kh = Ql + 128 * QP;
    bf16* Kl = Kh + 64 * QP;
    bf16* Vh = Kl + 64 * QP;
    bf16* Vl = Vh + 64 * QP;

    const int bh = blockIdx.y, q0 = blockIdx.x * 128;
    const int t = threadIdx.x, lane = t & 31, wid = t >> 5;
    const int m0w = wid * 16;
    const size_t bhoff = (size_t)bh * SS * AA;
    const uint32_t sb = smem_u32(smh);

    // load Q hi/lo
    {
        const bf16* Qghi = g_qhi + bhoff + (size_t)q0 * AA;
        const bf16* Qglo = g_qlo + bhoff + (size_t)q0 * AA;
        #pragma unroll
        for (int i = 0; i < 4; i++) {
            int idx = t + i * 256;      // 0..1023
            int row = idx >> 3, cq = idx & 7;
            *(uint4*)(Qh + row * QP + cq * 8) = *(const uint4*)(Qghi + row * AA + cq * 8);
            *(uint4*)(Ql + row * QP + cq * 8) = *(const uint4*)(Qglo + row * AA + cq * 8);
        }
    }

    float o[8][4];
    #pragma unroll
    for (int j = 0; j < 8; j++)
        #pragma unroll
        for (int i = 0; i < 4; i++) o[j][i] = 0.0f;
    float mi0 = -INFINITY, mi1 = -INFINITY, li0 = 0.0f, li1 = 0.0f;

    #pragma unroll 1
    for (int kt = 0; kt < SS / 64; kt++) {
        __syncthreads();
        {
            const size_t tileoff = bhoff + (size_t)kt * 64 * AA;
            const bf16* sKh = g_khi + tileoff;
            const bf16* sKl = g_klo + tileoff;
            const bf16* sVh = g_vhi + tileoff;
            const bf16* sVl = g_vlo + tileoff;
            #pragma unroll
            for (int i = 0; i < 2; i++) {
                int idx = t + i * 256;  // 0..511
                int row = idx >> 3, cq = idx & 7;
                int so = row * QP + cq * 8, go = row * AA + cq * 8;
                *(uint4*)(Kh + so) = *(const uint4*)(sKh + go);
                *(uint4*)(Kl + so) = *(const uint4*)(sKl + go);
                *(uint4*)(Vh + so) = *(const uint4*)(sVh + go);
                *(uint4*)(Vl + so) = *(const uint4*)(sVl + go);
            }
        }
        __syncthreads();

        // ---- S = Q K^T, split 3-term
        float s[8][4];
        #pragma unroll
        for (int j = 0; j < 8; j++)
            #pragma unroll
            for (int i = 0; i < 4; i++) s[j][i] = 0.0f;

        #pragma unroll
        for (int ka = 0; ka < 4; ka++) {
            const int a0 = ka * 16;
            uint32_t qh[4], ql[4];
            uint32_t qaddr = sb + ((m0w + (lane & 15)) * QP + a0 + (lane >> 4) * 8) * 2;
            ldsm4(qh, qaddr);
            ldsm4(ql, qaddr + OFF_QL);
            #pragma unroll
            for (int jp = 0; jp < 4; jp++) {
                uint32_t kh4[4], kl4[4];
                int krow = jp * 16 + (lane & 7) + ((lane & 16) ? 8 : 0);
                uint32_t kaddr = sb + OFF_KH + (krow * QP + a0 + ((lane >> 3) & 1) * 8) * 2;
                ldsm4(kh4, kaddr);
                ldsm4(kl4, kaddr + (OFF_KL - OFF_KH));
                mma16816(s[2*jp],   qh, &kh4[0]);
                mma16816(s[2*jp],   qh, &kl4[0]);
                mma16816(s[2*jp],   ql, &kh4[0]);
                mma16816(s[2*jp+1], qh, &kh4[2]);
                mma16816(s[2*jp+1], qh, &kl4[2]);
                mma16816(s[2*jp+1], ql, &kh4[2]);
            }
        }

        // ---- online softmax (rows g and g+8 per thread; lanes l=0..3 share a row)
        float tm0 = -INFINITY, tm1 = -INFINITY;
        #pragma unroll
        for (int j = 0; j < 8; j++) {
            tm0 = fmaxf(tm0, fmaxf(s[j][0], s[j][1]));
            tm1 = fmaxf(tm1, fmaxf(s[j][2], s[j][3]));
        }
        tm0 = fmaxf(tm0, __shfl_xor_sync(0xffffffffu, tm0, 1));
        tm0 = fmaxf(tm0, __shfl_xor_sync(0xffffffffu, tm0, 2));
        tm1 = fmaxf(tm1, __shfl_xor_sync(0xffffffffu, tm1, 1));
        tm1 = fmaxf(tm1, __shfl_xor_sync(0xffffffffu, tm1, 2));
        float mn0 = fmaxf(mi0, tm0), mn1 = fmaxf(mi1, tm1);
        float corr0 = fast_exp(mi0 - mn0), corr1 = fast_exp(mi1 - mn1);
        mi0 = mn0; mi1 = mn1;
        float rs0 = 0.0f, rs1 = 0.0f;
        #pragma unroll
        for (int j = 0; j < 8; j++) {
            s[j][0] = fast_exp(s[j][0] - mn0);
            s[j][1] = fast_exp(s[j][1] - mn0);
            s[j][2] = fast_exp(s[j][2] - mn1);
            s[j][3] = fast_exp(s[j][3] - mn1);
            rs0 += s[j][0] + s[j][1];
            rs1 += s[j][2] + s[j][3];
        }
        rs0 += __shfl_xor_sync(0xffffffffu, rs0, 1);
        rs0 += __shfl_xor_sync(0xffffffffu, rs0, 2);
        rs1 += __shfl_xor_sync(0xffffffffu, rs1, 1);
        rs1 += __shfl_xor_sync(0xffffffffu, rs1, 2);
        li0 = li0 * corr0 + rs0;
        li1 = li1 * corr1 + rs1;
        #pragma unroll
        for (int j = 0; j < 8; j++) {
            o[j][0] *= corr0; o[j][1] *= corr0;
            o[j][2] *= corr1; o[j][3] *= corr1;
        }

        // ---- O += P V, split 3-term (P packed from C-frags in regs)
        #pragma unroll
        for (int kc = 0; kc < 4; kc++) {
            uint32_t pah[4], pal[4];
            split2(s[2*kc][0],   s[2*kc][1],   pah[0], pal[0]);
            split2(s[2*kc][2],   s[2*kc][3],   pah[1], pal[1]);
            split2(s[2*kc+1][0], s[2*kc+1][1], pah[2], pal[2]);
            split2(s[2*kc+1][2], s[2*kc+1][3], pah[3], pal[3]);
            #pragma unroll
            for (int jp = 0; jp < 4; jp++) {
                uint32_t vh4[4], vl4[4];
                int vrow = kc * 16 + (lane & 7) + ((lane >> 3) & 1) * 8;
                uint32_t vaddr = sb + OFF_VH + (vrow * QP + jp * 16 + ((lane & 16) ? 8 : 0)) * 2;
                ldsm4t(vh4, vaddr);
                ldsm4t(vl4, vaddr + (OFF_VL - OFF_VH));
                mma16816(o[2*jp],   pah, &vh4[0]);
                mma16816(o[2*jp],   pah, &vl4[0]);
                mma16816(o[2*jp],   pal, &vh4[0]);
                mma16816(o[2*jp+1], pah, &vh4[2]);
                mma16816(o[2*jp+1], pah, &vl4[2]);
                mma16816(o[2*jp+1], pal, &vh4[2]);
            }
        }
    }

    // ---- epilogue: normalize, write [b, s, h*A + a]
    const float inv0 = 1.0f / li0, inv1 = 1.0f / li1;
    const int g = lane >> 2, l = lane & 3;
    const int b = bh >> 4, h = bh & 15;
    const int row0 = q0 + m0w + g;
    float* outp = out + ((size_t)b * SS + row0) * NN + h * AA;
    #pragma unroll
    for (int j = 0; j < 8; j++) {
        float2 w0 = make_float2(o[j][0] * inv0, o[j][1] * inv0);
        float2 w1 = make_float2(o[j][2] * inv1, o[j][3] * inv1);
        *(float2*)(outp + j * 8 + l * 2) = w0;
        *(float2*)(outp + (size_t)8 * NN + j * 8 + l * 2) = w1;
    }
}

extern "C" void kernel_launch(void* const* d_in, const int* in_sizes, int n_in,
                              void* d_out, int out_size) {
    (void)in_sizes; (void)n_in; (void)out_size;
    const float* q  = (const float*)d_in[0];
    const float* k  = (const float*)d_in[1];
    const float* v  = (const float*)d_in[2];
    const float* Wq = (const float*)d_in[3];
    const float* bq = (const float*)d_in[4];
    const float* Wk = (const float*)d_in[5];
    const float* bk = (const float*)d_in[6];
    const float* Wv = (const float*)d_in[7];
    const float* bv = (const float*)d_in[8];
    float* out = (float*)d_out;

    cudaFuncSetAttribute(proj_mma, cudaFuncAttributeMaxDynamicSharedMemorySize, PROJ_SMEM);
    cudaFuncSetAttribute(attn_mma, cudaFuncAttributeMaxDynamicSharedMemorySize, ATTN_SMEM);

    dim3 pg(64, 8);
    cvt_x<<<8192, 256>>>(q);
    cvt_w<<<1024, 256>>>(Wq);
    proj_mma<<<pg, 256, PROJ_SMEM>>>(bq, 0);

    cvt_x<<<8192, 256>>>(k);
    cvt_w<<<1024, 256>>>(Wk);
    proj_mma<<<pg, 256, PROJ_SMEM>>>(bk, 1);

    cvt_x<<<8192, 256>>>(v);
    cvt_w<<<1024, 256>>>(Wv);
    proj_mma<<<pg, 256, PROJ_SMEM>>>(bv, 2);

    dim3 ag(SS / 128, BB * HH);
    attn_mma<<<ag, 256, ATTN_SMEM>>>(out);
}

// round 5
// speedup vs baseline: 2.5787x; 1.1903x over previous
#include <cuda_runtime.h>
#include <cuda_bf16.h>
#include <math.h>
#include <stdint.h>

#define BB 4
#define SS 2048
#define DD 1024
#define HH 16
#define AA 64
#define NN (HH*AA)   // 1024

typedef __nv_bfloat16 bf16;
typedef __nv_bfloat162 bf162;

// ---- scratch: projected heads as bf16 hi/lo pairs, layout [b*H+h][s][a] ----
__device__ bf16 g_qhi[BB*HH*SS*AA];
__device__ bf16 g_qlo[BB*HH*SS*AA];
__device__ bf16 g_khi[BB*HH*SS*AA];
__device__ bf16 g_klo[BB*HH*SS*AA];
__device__ bf16 g_vhi[BB*HH*SS*AA];
__device__ bf16 g_vlo[BB*HH*SS*AA];
// inputs split
__device__ bf16 g_xhi[BB*SS*DD];
__device__ bf16 g_xlo[BB*SS*DD];
__device__ bf16 g_whi[NN*DD];
__device__ bf16 g_wlo[NN*DD];

// ======================= helpers =======================
__device__ __forceinline__ uint32_t smem_u32(const void* p) {
    uint32_t a;
    asm("{ .reg .u64 t; cvta.to.shared.u64 t, %1; cvt.u32.u64 %0, t; }" : "=r"(a) : "l"(p));
    return a;
}
__device__ __forceinline__ void mma16816(float* c, const uint32_t* a, const uint32_t* b) {
    asm volatile(
        "mma.sync.aligned.m16n8k16.row.col.f32.bf16.bf16.f32 "
        "{%0,%1,%2,%3}, {%4,%5,%6,%7}, {%8,%9}, {%0,%1,%2,%3};"
        : "+f"(c[0]), "+f"(c[1]), "+f"(c[2]), "+f"(c[3])
        : "r"(a[0]), "r"(a[1]), "r"(a[2]), "r"(a[3]), "r"(b[0]), "r"(b[1]));
}
__device__ __forceinline__ void ldsm4(uint32_t* r, uint32_t addr) {
    asm volatile("ldmatrix.sync.aligned.m8n8.x4.shared.b16 {%0,%1,%2,%3}, [%4];"
        : "=r"(r[0]), "=r"(r[1]), "=r"(r[2]), "=r"(r[3]) : "r"(addr));
}
__device__ __forceinline__ void ldsm4t(uint32_t* r, uint32_t addr) {
    asm volatile("ldmatrix.sync.aligned.m8n8.x4.trans.shared.b16 {%0,%1,%2,%3}, [%4];"
        : "=r"(r[0]), "=r"(r[1]), "=r"(r[2]), "=r"(r[3]) : "r"(addr));
}
#define CPA16(dst_u32, src_ptr) \
    asm volatile("cp.async.cg.shared.global [%0], [%1], 16;" :: "r"(dst_u32), "l"(src_ptr))
#define CPA_COMMIT() asm volatile("cp.async.commit_group;" ::: "memory")
#define CPA_WAIT(n)  asm volatile("cp.async.wait_group %0;" :: "n"(n) : "memory")

__device__ __forceinline__ void split2(float p0, float p1, uint32_t& hi, uint32_t& lo) {
    bf162 h = __floats2bfloat162_rn(p0, p1);
    bf162 l = __floats2bfloat162_rn(p0 - __bfloat162float(h.x), p1 - __bfloat162float(h.y));
    hi = *reinterpret_cast<uint32_t*>(&h);
    lo = *reinterpret_cast<uint32_t*>(&l);
}
// FFMA-only exp; valid for x <= 0 (and -inf)
__device__ __forceinline__ float fast_exp(float x) {
    float t = x * 1.4426950408889634f;
    t = fmaxf(t, -125.0f);
    int ii = __float2int_rn(t);
    float f = t - (float)ii;
    float p =              1.5252733e-5f;
    p = fmaf(p, f, 1.5403530e-4f);
    p = fmaf(p, f, 1.3333558e-3f);
    p = fmaf(p, f, 9.6181291e-3f);
    p = fmaf(p, f, 5.5504109e-2f);
    p = fmaf(p, f, 2.4022651e-1f);
    p = fmaf(p, f, 6.9314718e-1f);
    p = fmaf(p, f, 1.0f);
    return p * __int_as_float((ii + 127) << 23);
}

// ======================= conversion kernels =======================
__global__ __launch_bounds__(256) void cvt_x(const float* __restrict__ X) {
    int i = blockIdx.x * 256 + threadIdx.x;
    float4 x = ((const float4*)X)[i];
    bf16 h0 = __float2bfloat16(x.x), h1 = __float2bfloat16(x.y);
    bf16 h2 = __float2bfloat16(x.z), h3 = __float2bfloat16(x.w);
    bf16 l0 = __float2bfloat16(x.x - __bfloat162float(h0));
    bf16 l1 = __float2bfloat16(x.y - __bfloat162float(h1));
    bf16 l2 = __float2bfloat16(x.z - __bfloat162float(h2));
    bf16 l3 = __float2bfloat16(x.w - __bfloat162float(h3));
    bf162* ph = (bf162*)g_xhi;
    bf162* pl = (bf162*)g_xlo;
    ph[2*i]   = __halves2bfloat162(h0, h1);
    ph[2*i+1] = __halves2bfloat162(h2, h3);
    pl[2*i]   = __halves2bfloat162(l0, l1);
    pl[2*i+1] = __halves2bfloat162(l2, l3);
}
__global__ __launch_bounds__(256) void cvt_w(const float* __restrict__ W) {
    int idx = blockIdx.x * 256 + threadIdx.x;
    float4 wv = ((const float4*)W)[idx];
    int a4 = idx & 15;
    int d  = (idx >> 4) & 1023;
    int h  = idx >> 14;
    int nb = h * AA + a4 * 4;
    float vals[4] = {wv.x, wv.y, wv.z, wv.w};
    #pragma unroll
    for (int j = 0; j < 4; j++) {
        bf16 hi = __float2bfloat16(vals[j]);
        bf16 lo = __float2bfloat16(vals[j] - __bfloat162float(hi));
        size_t o = (size_t)(nb + j) * DD + d;
        g_whi[o] = hi;
        g_wlo[o] = lo;
    }
}

// ======================= projection GEMM (mma.sync, bf16-split, cp.async 2-stage) ===========
#define KC 32
#define XP 40                                  // padded stride (halves): 80B rows
#define PSTG_H (4*128*XP)                      // halves per stage
#define PSTG_B (PSTG_H*2)                      // 40960 bytes
#define PROJ_SMEM (2*PSTG_B)                   // 81920

__global__ __launch_bounds__(256) void proj_mma(const float* __restrict__ bias, int which) {
    bf16 *outhi, *outlo;
    if      (which == 0) { outhi = g_qhi; outlo = g_qlo; }
    else if (which == 1) { outhi = g_khi; outlo = g_klo; }
    else                 { outhi = g_vhi; outlo = g_vlo; }
    extern __shared__ bf16 sm[];
    const int t = threadIdx.x, lane = t & 31, wid = t >> 5;
    const int wm = wid & 1, wn = wid >> 1;
    const int r0 = blockIdx.x * 128, n0 = blockIdx.y * 128;
    const uint32_t sbase = smem_u32(sm);

    float c[4][4][4];
    #pragma unroll
    for (int mt = 0; mt < 4; mt++)
        #pragma unroll
        for (int nt = 0; nt < 4; nt++)
            #pragma unroll
            for (int i = 0; i < 4; i++) c[mt][nt][i] = 0.0f;

    // issue one K-chunk's loads (8 x cp.async 16B per thread)
#define PROJ_ISSUE(kc_) do {                                                       \
    int k0_ = (kc_) * KC;                                                          \
    uint32_t stg_ = sbase + ((kc_) & 1) * PSTG_B;                                  \
    _Pragma("unroll")                                                              \
    for (int i = 0; i < 8; i++) {                                                  \
        int rem = ((i & 1) << 8) + t; int row = rem >> 2, cq = rem & 3;            \
        const bf16* src;                                                           \
        if      ((i >> 1) == 0) src = g_xhi + (size_t)(r0 + row) * DD + k0_ + cq * 8; \
        else if ((i >> 1) == 1) src = g_xlo + (size_t)(r0 + row) * DD + k0_ + cq * 8; \
        else if ((i >> 1) == 2) src = g_whi + (size_t)(n0 + row) * DD + k0_ + cq * 8; \
        else                    src = g_wlo + (size_t)(n0 + row) * DD + k0_ + cq * 8; \
        uint32_t dst = stg_ + ((i >> 1) * (128 * XP) + row * XP + cq * 8) * 2;     \
        CPA16(dst, src);                                                           \
    } } while (0)

    PROJ_ISSUE(0);
    CPA_COMMIT();
    #pragma unroll 1
    for (int kc = 0; kc < DD / KC; kc++) {
        if (kc + 1 < DD / KC) {
            PROJ_ISSUE(kc + 1);
            CPA_COMMIT();
            CPA_WAIT(1);
        } else {
            CPA_WAIT(0);
        }
        __syncthreads();

        const uint32_t stage = sbase + (kc & 1) * PSTG_B;
        #pragma unroll
        for (int ka = 0; ka < 2; ka++) {
            const int kk = ka * 16;
            uint32_t xh[4][4], xl[4][4];
            #pragma unroll
            for (int mt = 0; mt < 4; mt++) {
                uint32_t addr = stage +
                    ((wm * 64 + mt * 16 + (lane & 15)) * XP + kk + (lane >> 4) * 8) * 2;
                ldsm4(xh[mt], addr);
                ldsm4(xl[mt], addr + 128 * XP * 2);
            }
            #pragma unroll
            for (int np = 0; np < 2; np++) {
                uint32_t wh[4], wl[4];
                int brow = wn * 32 + np * 16 + (lane & 7) + ((lane & 16) ? 8 : 0);
                uint32_t baddr = stage + (2 * 128 * XP) * 2 +
                    (brow * XP + kk + ((lane >> 3) & 1) * 8) * 2;
                ldsm4(wh, baddr);
                ldsm4(wl, baddr + 128 * XP * 2);
                #pragma unroll
                for (int mt = 0; mt < 4; mt++) {
                    mma16816(c[mt][2*np],   xh[mt], &wh[0]);
                    mma16816(c[mt][2*np],   xh[mt], &wl[0]);
                    mma16816(c[mt][2*np],   xl[mt], &wh[0]);
                    mma16816(c[mt][2*np+1], xh[mt], &wh[2]);
                    mma16816(c[mt][2*np+1], xh[mt], &wl[2]);
                    mma16816(c[mt][2*np+1], xl[mt], &wh[2]);
                }
            }
        }
        __syncthreads();
    }

    // epilogue: +bias, split to hi/lo bf16, store [b*H+h][s][a]
    const int g = lane >> 2, l = lane & 3;
    #pragma unroll
    for (int mt = 0; mt < 4; mt++) {
        int row = r0 + wm * 64 + mt * 16 + g;
        int b = row >> 11, s = row & (SS - 1);
        #pragma unroll
        for (int nt = 0; nt < 4; nt++) {
            int n = n0 + wn * 32 + nt * 8 + l * 2;
            int h = n >> 6, a = n & 63;
            size_t off = ((size_t)(b * HH + h) * SS + s) * AA + a;
            float bv0 = bias[n], bv1 = bias[n + 1];
            uint32_t hi, lo;
            split2(c[mt][nt][0] + bv0, c[mt][nt][1] + bv1, hi, lo);
            *(uint32_t*)(outhi + off) = hi;
            *(uint32_t*)(outlo + off) = lo;
            split2(c[mt][nt][2] + bv0, c[mt][nt][3] + bv1, hi, lo);
            *(uint32_t*)(outhi + off + 8 * AA) = hi;
            *(uint32_t*)(outlo + off + 8 * AA) = lo;
        }
    }
}

// ======================= flash attention (mma.sync, bf16-split, cp.async 2-stage K/V) =======
#define QP 72                                  // padded stride halves (144B rows)
#define ASTG_H (4*64*QP)                       // halves per K/V stage
#define ASTG_B (ASTG_H*2)                      // 36864 bytes
#define OFF_QL (128*QP*2)
#define OFF_ST (256*QP*2)                      // first stage byte offset
#define ATTN_SMEM (OFF_ST + 2*ASTG_B)          // 110592 bytes

__global__ __launch_bounds__(256) void attn_mma(float* __restrict__ out) {
    extern __shared__ bf16 smh[];
    bf16* Qh = smh;
    bf16* Ql = Qh + 128 * QP;

    const int bh = blockIdx.y, q0 = blockIdx.x * 128;
    const int t = threadIdx.x, lane = t & 31, wid = t >> 5;
    const int m0w = wid * 16;
    const size_t bhoff = (size_t)bh * SS * AA;
    const uint32_t sb = smem_u32(smh);

    // issue K/V hi/lo tile kt_ into stage (kt_&1): 8 x cp.async 16B per thread
#define ATTN_ISSUE(kt_) do {                                                      \
    const size_t toff_ = bhoff + (size_t)(kt_) * 64 * AA;                         \
    uint32_t stg_ = sb + OFF_ST + ((kt_) & 1) * ASTG_B;                           \
    _Pragma("unroll")                                                             \
    for (int i = 0; i < 2; i++) {                                                 \
        int idx = t + i * 256; int row = idx >> 3, cq = idx & 7;                  \
        uint32_t so = stg_ + (row * QP + cq * 8) * 2;                             \
        size_t go = toff_ + row * AA + cq * 8;                                    \
        CPA16(so,                    g_khi + go);                                 \
        CPA16(so + 64*QP*2,          g_klo + go);                                 \
        CPA16(so + 128*QP*2,         g_vhi + go);                                 \
        CPA16(so + 192*QP*2,         g_vlo + go);                                 \
    } } while (0)

    // load Q hi/lo (plain stores; covered by first loop barrier)
    {
        const bf16* Qghi = g_qhi + bhoff + (size_t)q0 * AA;
        const bf16* Qglo = g_qlo + bhoff + (size_t)q0 * AA;
        #pragma unroll
        for (int i = 0; i < 4; i++) {
            int idx = t + i * 256;
            int row = idx >> 3, cq = idx & 7;
            *(uint4*)(Qh + row * QP + cq * 8) = *(const uint4*)(Qghi + row * AA + cq * 8);
            *(uint4*)(Ql + row * QP + cq * 8) = *(const uint4*)(Qglo + row * AA + cq * 8);
        }
    }

    ATTN_ISSUE(0);
    CPA_COMMIT();

    float o[8][4];
    #pragma unroll
    for (int j = 0; j < 8; j++)
        #pragma unroll
        for (int i = 0; i < 4; i++) o[j][i] = 0.0f;
    float mi0 = -INFINITY, mi1 = -INFINITY, li0 = 0.0f, li1 = 0.0f;

    #pragma unroll 1
    for (int kt = 0; kt < SS / 64; kt++) {
        if (kt + 1 < SS / 64) {
            ATTN_ISSUE(kt + 1);
            CPA_COMMIT();
            CPA_WAIT(1);
        } else {
            CPA_WAIT(0);
        }
        __syncthreads();
        const uint32_t stg = sb + OFF_ST + (kt & 1) * ASTG_B;

        // ---- S = Q K^T, split 3-term
        float s[8][4];
        #pragma unroll
        for (int j = 0; j < 8; j++)
            #pragma unroll
            for (int i = 0; i < 4; i++) s[j][i] = 0.0f;

        #pragma unroll
        for (int ka = 0; ka < 4; ka++) {
            const int a0 = ka * 16;
            uint32_t qh[4], ql[4];
            uint32_t qaddr = sb + ((m0w + (lane & 15)) * QP + a0 + (lane >> 4) * 8) * 2;
            ldsm4(qh, qaddr);
            ldsm4(ql, qaddr + OFF_QL);
            #pragma unroll
            for (int jp = 0; jp < 4; jp++) {
                uint32_t kh4[4], kl4[4];
                int krow = jp * 16 + (lane & 7) + ((lane & 16) ? 8 : 0);
                uint32_t kaddr = stg + (krow * QP + a0 + ((lane >> 3) & 1) * 8) * 2;
                ldsm4(kh4, kaddr);
                ldsm4(kl4, kaddr + 64 * QP * 2);
                mma16816(s[2*jp],   qh, &kh4[0]);
                mma16816(s[2*jp],   qh, &kl4[0]);
                mma16816(s[2*jp],   ql, &kh4[0]);
                mma16816(s[2*jp+1], qh, &kh4[2]);
                mma16816(s[2*jp+1], qh, &kl4[2]);
                mma16816(s[2*jp+1], ql, &kh4[2]);
            }
        }

        // ---- online softmax (rows g and g+8; lanes l=0..3 share a row)
        float tm0 = -INFINITY, tm1 = -INFINITY;
        #pragma unroll
        for (int j = 0; j < 8; j++) {
            tm0 = fmaxf(tm0, fmaxf(s[j][0], s[j][1]));
            tm1 = fmaxf(tm1, fmaxf(s[j][2], s[j][3]));
        }
        tm0 = fmaxf(tm0, __shfl_xor_sync(0xffffffffu, tm0, 1));
        tm0 = fmaxf(tm0, __shfl_xor_sync(0xffffffffu, tm0, 2));
        tm1 = fmaxf(tm1, __shfl_xor_sync(0xffffffffu, tm1, 1));
        tm1 = fmaxf(tm1, __shfl_xor_sync(0xffffffffu, tm1, 2));
        float mn0 = fmaxf(mi0, tm0), mn1 = fmaxf(mi1, tm1);
        float corr0 = fast_exp(mi0 - mn0), corr1 = fast_exp(mi1 - mn1);
        mi0 = mn0; mi1 = mn1;
        float rs0 = 0.0f, rs1 = 0.0f;
        #pragma unroll
        for (int j = 0; j < 8; j++) {
            s[j][0] = fast_exp(s[j][0] - mn0);
            s[j][1] = fast_exp(s[j][1] - mn0);
            s[j][2] = fast_exp(s[j][2] - mn1);
            s[j][3] = fast_exp(s[j][3] - mn1);
            rs0 += s[j][0] + s[j][1];
            rs1 += s[j][2] + s[j][3];
        }
        rs0 += __shfl_xor_sync(0xffffffffu, rs0, 1);
        rs0 += __shfl_xor_sync(0xffffffffu, rs0, 2);
        rs1 += __shfl_xor_sync(0xffffffffu, rs1, 1);
        rs1 += __shfl_xor_sync(0xffffffffu, rs1, 2);
        li0 = li0 * corr0 + rs0;
        li1 = li1 * corr1 + rs1;
        #pragma unroll
        for (int j = 0; j < 8; j++) {
            o[j][0] *= corr0; o[j][1] *= corr0;
            o[j][2] *= corr1; o[j][3] *= corr1;
        }

        // ---- O += P V, split 3-term (P packed from C-frags in regs)
        #pragma unroll
        for (int kc = 0; kc < 4; kc++) {
            uint32_t pah[4], pal[4];
            split2(s[2*kc][0],   s[2*kc][1],   pah[0], pal[0]);
            split2(s[2*kc][2],   s[2*kc][3],   pah[1], pal[1]);
            split2(s[2*kc+1][0], s[2*kc+1][1], pah[2], pal[2]);
            split2(s[2*kc+1][2], s[2*kc+1][3], pah[3], pal[3]);
            #pragma unroll
            for (int jp = 0; jp < 4; jp++) {
                uint32_t vh4[4], vl4[4];
                int vrow = kc * 16 + (lane & 7) + ((lane >> 3) & 1) * 8;
                uint32_t vaddr = stg + 128 * QP * 2 +
                    (vrow * QP + jp * 16 + ((lane & 16) ? 8 : 0)) * 2;
                ldsm4t(vh4, vaddr);
                ldsm4t(vl4, vaddr + 64 * QP * 2);
                mma16816(o[2*jp],   pah, &vh4[0]);
                mma16816(o[2*jp],   pah, &vl4[0]);
                mma16816(o[2*jp],   pal, &vh4[0]);
                mma16816(o[2*jp+1], pah, &vh4[2]);
                mma16816(o[2*jp+1], pah, &vl4[2]);
                mma16816(o[2*jp+1], pal, &vh4[2]);
            }
        }
        __syncthreads();
    }

    // ---- epilogue: normalize, write [b, s, h*A + a]
    const float inv0 = 1.0f / li0, inv1 = 1.0f / li1;
    const int g = lane >> 2, l = lane & 3;
    const int b = bh >> 4, h = bh & 15;
    const int row0 = q0 + m0w + g;
    float* outp = out + ((size_t)b * SS + row0) * NN + h * AA;
    #pragma unroll
    for (int j = 0; j < 8; j++) {
        float2 w0 = make_float2(o[j][0] * inv0, o[j][1] * inv0);
        float2 w1 = make_float2(o[j][2] * inv1, o[j][3] * inv1);
        *(float2*)(outp + j * 8 + l * 2) = w0;
        *(float2*)(outp + (size_t)8 * NN + j * 8 + l * 2) = w1;
    }
}

extern "C" void kernel_launch(void* const* d_in, const int* in_sizes, int n_in,
                              void* d_out, int out_size) {
    (void)in_sizes; (void)n_in; (void)out_size;
    const float* q  = (const float*)d_in[0];
    const float* k  = (const float*)d_in[1];
    const float* v  = (const float*)d_in[2];
    const float* Wq = (const float*)d_in[3];
    const float* bq = (const float*)d_in[4];
    const float* Wk = (const float*)d_in[5];
    const float* bk = (const float*)d_in[6];
    const float* Wv = (const float*)d_in[7];
    const float* bv = (const float*)d_in[8];
    float* out = (float*)d_out;

    cudaFuncSetAttribute(proj_mma, cudaFuncAttributeMaxDynamicSharedMemorySize, PROJ_SMEM);
    cudaFuncSetAttribute(attn_mma, cudaFuncAttributeMaxDynamicSharedMemorySize, ATTN_SMEM);

    dim3 pg(64, 8);
    cvt_x<<<8192, 256>>>(q);
    cvt_w<<<1024, 256>>>(Wq);
    proj_mma<<<pg, 256, PROJ_SMEM>>>(bq, 0);

    cvt_x<<<8192, 256>>>(k);
    cvt_w<<<1024, 256>>>(Wk);
    proj_mma<<<pg, 256, PROJ_SMEM>>>(bk, 1);

    cvt_x<<<8192, 256>>>(v);
    cvt_w<<<1024, 256>>>(Wv);
    proj_mma<<<pg, 256, PROJ_SMEM>>>(bv, 2);

    dim3 ag(SS / 128, BB * HH);
    attn_mma<<<ag, 256, ATTN_SMEM>>>(out);
}

// round 6
// speedup vs baseline: 3.4833x; 1.3508x over previous
#include <cuda_runtime.h>
#include <cuda_bf16.h>
#include <cuda_fp16.h>
#include <math.h>
#include <stdint.h>

#define BB 4
#define SS 2048
#define DD 1024
#define HH 16
#define AA 64
#define NN (HH*AA)   // 1024
#define BSD (BB*SS*DD)

typedef __nv_bfloat16 bf16;
typedef __nv_bfloat162 bf162;

// ---- scratch ----
__device__ bf16 g_qhi[BB*HH*SS*AA];
__device__ bf16 g_qlo[BB*HH*SS*AA];
__device__ bf16 g_khi[BB*HH*SS*AA];
__device__ bf16 g_klo[BB*HH*SS*AA];
__device__ __half g_vh2[BB*HH*SS*AA];        // V single fp16
__device__ bf16 g_xhi[3*BSD];
__device__ bf16 g_xlo[3*BSD];
__device__ bf16 g_whi[3*NN*DD];
__device__ bf16 g_wlo[3*NN*DD];

// ======================= helpers =======================
__device__ __forceinline__ uint32_t smem_u32(const void* p) {
    uint32_t a;
    asm("{ .reg .u64 t; cvta.to.shared.u64 t, %1; cvt.u32.u64 %0, t; }" : "=r"(a) : "l"(p));
    return a;
}
__device__ __forceinline__ void mma16816(float* c, const uint32_t* a, const uint32_t* b) {
    asm volatile(
        "mma.sync.aligned.m16n8k16.row.col.f32.bf16.bf16.f32 "
        "{%0,%1,%2,%3}, {%4,%5,%6,%7}, {%8,%9}, {%0,%1,%2,%3};"
        : "+f"(c[0]), "+f"(c[1]), "+f"(c[2]), "+f"(c[3])
        : "r"(a[0]), "r"(a[1]), "r"(a[2]), "r"(a[3]), "r"(b[0]), "r"(b[1]));
}
__device__ __forceinline__ void mma16816h(float* c, const uint32_t* a, const uint32_t* b) {
    asm volatile(
        "mma.sync.aligned.m16n8k16.row.col.f32.f16.f16.f32 "
        "{%0,%1,%2,%3}, {%4,%5,%6,%7}, {%8,%9}, {%0,%1,%2,%3};"
        : "+f"(c[0]), "+f"(c[1]), "+f"(c[2]), "+f"(c[3])
        : "r"(a[0]), "r"(a[1]), "r"(a[2]), "r"(a[3]), "r"(b[0]), "r"(b[1]));
}
__device__ __forceinline__ void ldsm4(uint32_t* r, uint32_t addr) {
    asm volatile("ldmatrix.sync.aligned.m8n8.x4.shared.b16 {%0,%1,%2,%3}, [%4];"
        : "=r"(r[0]), "=r"(r[1]), "=r"(r[2]), "=r"(r[3]) : "r"(addr));
}
__device__ __forceinline__ void ldsm4t(uint32_t* r, uint32_t addr) {
    asm volatile("ldmatrix.sync.aligned.m8n8.x4.trans.shared.b16 {%0,%1,%2,%3}, [%4];"
        : "=r"(r[0]), "=r"(r[1]), "=r"(r[2]), "=r"(r[3]) : "r"(addr));
}
#define CPA16(dst_u32, src_ptr) \
    asm volatile("cp.async.cg.shared.global [%0], [%1], 16;" :: "r"(dst_u32), "l"(src_ptr))
#define CPA_COMMIT() asm volatile("cp.async.commit_group;" ::: "memory")
#define CPA_WAIT(n)  asm volatile("cp.async.wait_group %0;" :: "n"(n) : "memory")

__device__ __forceinline__ float ex2f(float x) {
    float r;
    asm("ex2.approx.f32 %0, %1;" : "=f"(r) : "f"(x));
    return r;
}
__device__ __forceinline__ uint32_t packh2(float a, float b) {
    __half2 h = __floats2half2_rn(a, b);      // x = a (low), y = b (high)
    return *reinterpret_cast<uint32_t*>(&h);
}
__device__ __forceinline__ void split2(float p0, float p1, uint32_t& hi, uint32_t& lo) {
    bf162 h = __floats2bfloat162_rn(p0, p1);
    bf162 l = __floats2bfloat162_rn(p0 - __bfloat162float(h.x), p1 - __bfloat162float(h.y));
    hi = *reinterpret_cast<uint32_t*>(&h);
    lo = *reinterpret_cast<uint32_t*>(&l);
}
#define L2E 1.4426950408889634f

// ======================= conversion kernels (fused over q,k,v) =======================
__global__ __launch_bounds__(256) void cvt_x3(const float* __restrict__ q,
                                              const float* __restrict__ k,
                                              const float* __restrict__ v) {
    const int which = blockIdx.y;
    const float* X = (which == 0) ? q : (which == 1) ? k : v;
    bf16* xh = g_xhi + (size_t)which * BSD;
    bf16* xl = g_xlo + (size_t)which * BSD;
    int i = blockIdx.x * 256 + threadIdx.x;
    float4 x = ((const float4*)X)[i];
    bf16 h0 = __float2bfloat16(x.x), h1 = __float2bfloat16(x.y);
    bf16 h2 = __float2bfloat16(x.z), h3 = __float2bfloat16(x.w);
    bf16 l0 = __float2bfloat16(x.x - __bfloat162float(h0));
    bf16 l1 = __float2bfloat16(x.y - __bfloat162float(h1));
    bf16 l2 = __float2bfloat16(x.z - __bfloat162float(h2));
    bf16 l3 = __float2bfloat16(x.w - __bfloat162float(h3));
    bf162* ph = (bf162*)xh;
    bf162* pl = (bf162*)xl;
    ph[2*i]   = __halves2bfloat162(h0, h1);
    ph[2*i+1] = __halves2bfloat162(h2, h3);
    pl[2*i]   = __halves2bfloat162(l0, l1);
    pl[2*i+1] = __halves2bfloat162(l2, l3);
}
__global__ __launch_bounds__(256) void cvt_w3(const float* __restrict__ Wq,
                                              const float* __restrict__ Wk,
                                              const float* __restrict__ Wv) {
    const int which = blockIdx.y;
    const float* W = (which == 0) ? Wq : (which == 1) ? Wk : Wv;
    bf16* wh = g_whi + (size_t)which * (NN * DD);
    bf16* wl = g_wlo + (size_t)which * (NN * DD);
    int idx = blockIdx.x * 256 + threadIdx.x;
    float4 wv = ((const float4*)W)[idx];
    int a4 = idx & 15;
    int d  = (idx >> 4) & 1023;
    int h  = idx >> 14;
    int nb = h * AA + a4 * 4;
    float vals[4] = {wv.x, wv.y, wv.z, wv.w};
    #pragma unroll
    for (int j = 0; j < 4; j++) {
        bf16 hi = __float2bfloat16(vals[j]);
        bf16 lo = __float2bfloat16(vals[j] - __bfloat162float(hi));
        size_t o = (size_t)(nb + j) * DD + d;
        wh[o] = hi;
        wl[o] = lo;
    }
}

// ======================= projection GEMM (fused q/k/v, bf16-split, cp.async 2-stage) ========
#define KC 32
#define XP 40
#define PSTG_H (4*128*XP)
#define PSTG_B (PSTG_H*2)                      // 40960 bytes
#define PROJ_SMEM (2*PSTG_B)                   // 81920

__global__ __launch_bounds__(256, 2) void proj_mma(const float* __restrict__ bq,
                                                   const float* __restrict__ bk,
                                                   const float* __restrict__ bv) {
    const int which = blockIdx.z;
    const float* bias = (which == 0) ? bq : (which == 1) ? bk : bv;
    const bf16* Xh = g_xhi + (size_t)which * BSD;
    const bf16* Xl = g_xlo + (size_t)which * BSD;
    const bf16* Wh = g_whi + (size_t)which * (NN * DD);
    const bf16* Wl = g_wlo + (size_t)which * (NN * DD);
    extern __shared__ bf16 sm[];
    const int t = threadIdx.x, lane = t & 31, wid = t >> 5;
    const int wm = wid & 1, wn = wid >> 1;
    const int r0 = blockIdx.x * 128, n0 = blockIdx.y * 128;
    const uint32_t sbase = smem_u32(sm);

    float c[4][4][4];
    #pragma unroll
    for (int mt = 0; mt < 4; mt++)
        #pragma unroll
        for (int nt = 0; nt < 4; nt++)
            #pragma unroll
            for (int i = 0; i < 4; i++) c[mt][nt][i] = 0.0f;

#define PROJ_ISSUE(kc_) do {                                                       \
    int k0_ = (kc_) * KC;                                                          \
    uint32_t stg_ = sbase + ((kc_) & 1) * PSTG_B;                                  \
    _Pragma("unroll")                                                              \
    for (int i = 0; i < 8; i++) {                                                  \
        int rem = ((i & 1) << 8) + t; int row = rem >> 2, cq = rem & 3;            \
        const bf16* src;                                                           \
        if      ((i >> 1) == 0) src = Xh + (size_t)(r0 + row) * DD + k0_ + cq * 8; \
        else if ((i >> 1) == 1) src = Xl + (size_t)(r0 + row) * DD + k0_ + cq * 8; \
        else if ((i >> 1) == 2) src = Wh + (size_t)(n0 + row) * DD + k0_ + cq * 8; \
        else                    src = Wl + (size_t)(n0 + row) * DD + k0_ + cq * 8; \
        uint32_t dst = stg_ + ((i >> 1) * (128 * XP) + row * XP + cq * 8) * 2;     \
        CPA16(dst, src);                                                           \
    } } while (0)

    PROJ_ISSUE(0);
    CPA_COMMIT();
    #pragma unroll 1
    for (int kc = 0; kc < DD / KC; kc++) {
        if (kc + 1 < DD / KC) {
            PROJ_ISSUE(kc + 1);
            CPA_COMMIT();
            CPA_WAIT(1);
        } else {
            CPA_WAIT(0);
        }
        __syncthreads();

        const uint32_t stage = sbase + (kc & 1) * PSTG_B;
        #pragma unroll
        for (int ka = 0; ka < 2; ka++) {
            const int kk = ka * 16;
            uint32_t xh[4][4], xl[4][4];
            #pragma unroll
            for (int mt = 0; mt < 4; mt++) {
                uint32_t addr = stage +
                    ((wm * 64 + mt * 16 + (lane & 15)) * XP + kk + (lane >> 4) * 8) * 2;
                ldsm4(xh[mt], addr);
                ldsm4(xl[mt], addr + 128 * XP * 2);
            }
            #pragma unroll
            for (int np = 0; np < 2; np++) {
                uint32_t wh[4], wl[4];
                int brow = wn * 32 + np * 16 + (lane & 7) + ((lane & 16) ? 8 : 0);
                uint32_t baddr = stage + (2 * 128 * XP) * 2 +
                    (brow * XP + kk + ((lane >> 3) & 1) * 8) * 2;
                ldsm4(wh, baddr);
                ldsm4(wl, baddr + 128 * XP * 2);
                #pragma unroll
                for (int mt = 0; mt < 4; mt++) {
                    mma16816(c[mt][2*np],   xh[mt], &wh[0]);
                    mma16816(c[mt][2*np],   xh[mt], &wl[0]);
                    mma16816(c[mt][2*np],   xl[mt], &wh[0]);
                    mma16816(c[mt][2*np+1], xh[mt], &wh[2]);
                    mma16816(c[mt][2*np+1], xh[mt], &wl[2]);
                    mma16816(c[mt][2*np+1], xl[mt], &wh[2]);
                }
            }
        }
        __syncthreads();
    }

    // epilogue
    const int g = lane >> 2, l = lane & 3;
    #pragma unroll
    for (int mt = 0; mt < 4; mt++) {
        int row = r0 + wm * 64 + mt * 16 + g;
        int b = row >> 11, s = row & (SS - 1);
        #pragma unroll
        for (int nt = 0; nt < 4; nt++) {
            int n = n0 + wn * 32 + nt * 8 + l * 2;
            int h = n >> 6, a = n & 63;
            size_t off = ((size_t)(b * HH + h) * SS + s) * AA + a;
            float bv0 = bias[n], bv1 = bias[n + 1];
            float p0 = c[mt][nt][0] + bv0, p1 = c[mt][nt][1] + bv1;
            float p2 = c[mt][nt][2] + bv0, p3 = c[mt][nt][3] + bv1;
            if (which == 2) {
                *(uint32_t*)(g_vh2 + off)          = packh2(p0, p1);
                *(uint32_t*)(g_vh2 + off + 8 * AA) = packh2(p2, p3);
            } else {
                bf16 *outhi = (which == 0) ? g_qhi : g_khi;
                bf16 *outlo = (which == 0) ? g_qlo : g_klo;
                uint32_t hi, lo;
                split2(p0, p1, hi, lo);
                *(uint32_t*)(outhi + off) = hi;
                *(uint32_t*)(outlo + off) = lo;
                split2(p2, p3, hi, lo);
                *(uint32_t*)(outhi + off + 8 * AA) = hi;
                *(uint32_t*)(outlo + off + 8 * AA) = lo;
            }
        }
    }
}

// ======================= flash attention =======================
// S: bf16 3-term split (precision-critical). PV: fp16 P x fp16 V, single term.
#define QP 72
#define ASTG_H (3*64*QP)                       // Khi, Klo, V
#define ASTG_B (ASTG_H*2)                      // 27648 bytes
#define OFF_QL (128*QP*2)
#define OFF_ST (256*QP*2)                      // 36864
#define ATTN_SMEM (OFF_ST + 2*ASTG_B)          // 92160 bytes

__global__ __launch_bounds__(256, 2) void attn_mma(float* __restrict__ out) {
    extern __shared__ bf16 smh[];
    bf16* Qh = smh;
    bf16* Ql = Qh + 128 * QP;

    const int bh = blockIdx.y, q0 = blockIdx.x * 128;
    const int t = threadIdx.x, lane = t & 31, wid = t >> 5;
    const int m0w = wid * 16;
    const size_t bhoff = (size_t)bh * SS * AA;
    const uint32_t sb = smem_u32(smh);

#define ATTN_ISSUE(kt_) do {                                                      \
    const size_t toff_ = bhoff + (size_t)(kt_) * 64 * AA;                         \
    uint32_t stg_ = sb + OFF_ST + ((kt_) & 1) * ASTG_B;                           \
    _Pragma("unroll")                                                             \
    for (int i = 0; i < 2; i++) {                                                 \
        int idx = t + i * 256; int row = idx >> 3, cq = idx & 7;                  \
        uint32_t so = stg_ + (row * QP + cq * 8) * 2;                             \
        size_t go = toff_ + row * AA + cq * 8;                                    \
        CPA16(so,              g_khi + go);                                       \
        CPA16(so + 64*QP*2,    g_klo + go);                                       \
        CPA16(so + 128*QP*2,   g_vh2 + go);                                       \
    } } while (0)

    // load Q hi/lo
    {
        const bf16* Qghi = g_qhi + bhoff + (size_t)q0 * AA;
        const bf16* Qglo = g_qlo + bhoff + (size_t)q0 * AA;
        #pragma unroll
        for (int i = 0; i < 4; i++) {
            int idx = t + i * 256;
            int row = idx >> 3, cq = idx & 7;
            *(uint4*)(Qh + row * QP + cq * 8) = *(const uint4*)(Qghi + row * AA + cq * 8);
            *(uint4*)(Ql + row * QP + cq * 8) = *(const uint4*)(Qglo + row * AA + cq * 8);
        }
    }

    ATTN_ISSUE(0);
    CPA_COMMIT();

    float o[8][4];
    #pragma unroll
    for (int j = 0; j < 8; j++)
        #pragma unroll
        for (int i = 0; i < 4; i++) o[j][i] = 0.0f;
    float mi0 = -INFINITY, mi1 = -INFINITY, li0 = 0.0f, li1 = 0.0f;

    #pragma unroll 1
    for (int kt = 0; kt < SS / 64; kt++) {
        if (kt + 1 < SS / 64) {
            ATTN_ISSUE(kt + 1);
            CPA_COMMIT();
            CPA_WAIT(1);
        } else {
            CPA_WAIT(0);
        }
        __syncthreads();
        const uint32_t stg = sb + OFF_ST + (kt & 1) * ASTG_B;

        // ---- S = Q K^T, bf16 3-term split
        float s[8][4];
        #pragma unroll
        for (int j = 0; j < 8; j++)
            #pragma unroll
            for (int i = 0; i < 4; i++) s[j][i] = 0.0f;

        #pragma unroll
        for (int ka = 0; ka < 4; ka++) {
            const int a0 = ka * 16;
            uint32_t qh[4], ql[4];
            uint32_t qaddr = sb + ((m0w + (lane & 15)) * QP + a0 + (lane >> 4) * 8) * 2;
            ldsm4(qh, qaddr);
            ldsm4(ql, qaddr + OFF_QL);
            #pragma unroll
            for (int jp = 0; jp < 4; jp++) {
                uint32_t kh4[4], kl4[4];
                int krow = jp * 16 + (lane & 7) + ((lane & 16) ? 8 : 0);
                uint32_t kaddr = stg + (krow * QP + a0 + ((lane >> 3) & 1) * 8) * 2;
                ldsm4(kh4, kaddr);
                ldsm4(kl4, kaddr + 64 * QP * 2);
                mma16816(s[2*jp],   qh, &kh4[0]);
                mma16816(s[2*jp],   qh, &kl4[0]);
                mma16816(s[2*jp],   ql, &kh4[0]);
                mma16816(s[2*jp+1], qh, &kh4[2]);
                mma16816(s[2*jp+1], qh, &kl4[2]);
                mma16816(s[2*jp+1], ql, &kh4[2]);
            }
        }

        // ---- online softmax (MUFU.EX2)
        float tm0 = -INFINITY, tm1 = -INFINITY;
        #pragma unroll
        for (int j = 0; j < 8; j++) {
            tm0 = fmaxf(tm0, fmaxf(s[j][0], s[j][1]));
            tm1 = fmaxf(tm1, fmaxf(s[j][2], s[j][3]));
        }
        tm0 = fmaxf(tm0, __shfl_xor_sync(0xffffffffu, tm0, 1));
        tm0 = fmaxf(tm0, __shfl_xor_sync(0xffffffffu, tm0, 2));
        tm1 = fmaxf(tm1, __shfl_xor_sync(0xffffffffu, tm1, 1));
        tm1 = fmaxf(tm1, __shfl_xor_sync(0xffffffffu, tm1, 2));
        float mn0 = fmaxf(mi0, tm0), mn1 = fmaxf(mi1, tm1);
        float corr0 = ex2f((mi0 - mn0) * L2E);
        float corr1 = ex2f((mi1 - mn1) * L2E);
        mi0 = mn0; mi1 = mn1;
        const float b0 = -mn0 * L2E, b1 = -mn1 * L2E;
        float rs0 = 0.0f, rs1 = 0.0f;
        #pragma unroll
        for (int j = 0; j < 8; j++) {
            s[j][0] = ex2f(fmaf(s[j][0], L2E, b0));
            s[j][1] = ex2f(fmaf(s[j][1], L2E, b0));
            s[j][2] = ex2f(fmaf(s[j][2], L2E, b1));
            s[j][3] = ex2f(fmaf(s[j][3], L2E, b1));
            rs0 += s[j][0] + s[j][1];
            rs1 += s[j][2] + s[j][3];
        }
        rs0 += __shfl_xor_sync(0xffffffffu, rs0, 1);
        rs0 += __shfl_xor_sync(0xffffffffu, rs0, 2);
        rs1 += __shfl_xor_sync(0xffffffffu, rs1, 1);
        rs1 += __shfl_xor_sync(0xffffffffu, rs1, 2);
        li0 = fmaf(li0, corr0, rs0);
        li1 = fmaf(li1, corr1, rs1);
        #pragma unroll
        for (int j = 0; j < 8; j++) {
            o[j][0] *= corr0; o[j][1] *= corr0;
            o[j][2] *= corr1; o[j][3] *= corr1;
        }

        // ---- O += P V  (fp16 x fp16, single term)
        #pragma unroll
        for (int kc = 0; kc < 4; kc++) {
            uint32_t pa[4];
            pa[0] = packh2(s[2*kc][0],   s[2*kc][1]);
            pa[1] = packh2(s[2*kc][2],   s[2*kc][3]);
            pa[2] = packh2(s[2*kc+1][0], s[2*kc+1][1]);
            pa[3] = packh2(s[2*kc+1][2], s[2*kc+1][3]);
            #pragma unroll
            for (int jp = 0; jp < 4; jp++) {
                uint32_t vh4[4];
                int vrow = kc * 16 + (lane & 7) + ((lane >> 3) & 1) * 8;
                uint32_t vaddr = stg + 128 * QP * 2 +
                    (vrow * QP + jp * 16 + ((lane & 16) ? 8 : 0)) * 2;
                ldsm4t(vh4, vaddr);
                mma16816h(o[2*jp],   pa, &vh4[0]);
                mma16816h(o[2*jp+1], pa, &vh4[2]);
            }
        }
        __syncthreads();
    }

    // ---- epilogue
    const float inv0 = 1.0f / li0, inv1 = 1.0f / li1;
    const int g = lane >> 2, l = lane & 3;
    const int b = bh >> 4, h = bh & 15;
    const int row0 = q0 + m0w + g;
    float* outp = out + ((size_t)b * SS + row0) * NN + h * AA;
    #pragma unroll
    for (int j = 0; j < 8; j++) {
        float2 w0 = make_float2(o[j][0] * inv0, o[j][1] * inv0);
        float2 w1 = make_float2(o[j][2] * inv1, o[j][3] * inv1);
        *(float2*)(outp + j * 8 + l * 2) = w0;
        *(float2*)(outp + (size_t)8 * NN + j * 8 + l * 2) = w1;
    }
}

extern "C" void kernel_launch(void* const* d_in, const int* in_sizes, int n_in,
                              void* d_out, int out_size) {
    (void)in_sizes; (void)n_in; (void)out_size;
    const float* q  = (const float*)d_in[0];
    const float* k  = (const float*)d_in[1];
    const float* v  = (const float*)d_in[2];
    const float* Wq = (const float*)d_in[3];
    const float* bq = (const float*)d_in[4];
    const float* Wk = (const float*)d_in[5];
    const float* bk = (const float*)d_in[6];
    const float* Wv = (const float*)d_in[7];
    const float* bv = (const float*)d_in[8];
    float* out = (float*)d_out;

    cudaFuncSetAttribute(proj_mma, cudaFuncAttributeMaxDynamicSharedMemorySize, PROJ_SMEM);
    cudaFuncSetAttribute(attn_mma, cudaFuncAttributeMaxDynamicSharedMemorySize, ATTN_SMEM);

    cvt_x3<<<dim3(8192, 3), 256>>>(q, k, v);
    cvt_w3<<<dim3(1024, 3), 256>>>(Wq, Wk, Wv);
    proj_mma<<<dim3(64, 8, 3), 256, PROJ_SMEM>>>(bq, bk, bv);

    dim3 ag(SS / 128, BB * HH);
    attn_mma<<<ag, 256, ATTN_SMEM>>>(out);
}

// round 7
// speedup vs baseline: 3.5709x; 1.0251x over previous
#include <cuda_runtime.h>
#include <cuda_bf16.h>
#include <cuda_fp16.h>
#include <math.h>
#include <stdint.h>

#define BB 4
#define SS 2048
#define DD 1024
#define HH 16
#define AA 64
#define NN (HH*AA)   // 1024
#define BSD (BB*SS*DD)

typedef __nv_bfloat16 bf16;
typedef __nv_bfloat162 bf162;

// ---- scratch ----
__device__ bf16 g_qhi[BB*HH*SS*AA];
__device__ bf16 g_qlo[BB*HH*SS*AA];
__device__ bf16 g_khi[BB*HH*SS*AA];
__device__ bf16 g_klo[BB*HH*SS*AA];
__device__ __half g_vh2[BB*HH*SS*AA];        // V single fp16
__device__ bf16 g_xhi[3*BSD];
__device__ bf16 g_xlo[3*BSD];
__device__ bf16 g_whi[3*NN*DD];
__device__ bf16 g_wlo[3*NN*DD];

// ======================= helpers =======================
__device__ __forceinline__ uint32_t smem_u32(const void* p) {
    uint32_t a;
    asm("{ .reg .u64 t; cvta.to.shared.u64 t, %1; cvt.u32.u64 %0, t; }" : "=r"(a) : "l"(p));
    return a;
}
__device__ __forceinline__ void mma16816(float* c, const uint32_t* a, const uint32_t* b) {
    asm volatile(
        "mma.sync.aligned.m16n8k16.row.col.f32.bf16.bf16.f32 "
        "{%0,%1,%2,%3}, {%4,%5,%6,%7}, {%8,%9}, {%0,%1,%2,%3};"
        : "+f"(c[0]), "+f"(c[1]), "+f"(c[2]), "+f"(c[3])
        : "r"(a[0]), "r"(a[1]), "r"(a[2]), "r"(a[3]), "r"(b[0]), "r"(b[1]));
}
__device__ __forceinline__ void mma16816h(float* c, const uint32_t* a, const uint32_t* b) {
    asm volatile(
        "mma.sync.aligned.m16n8k16.row.col.f32.f16.f16.f32 "
        "{%0,%1,%2,%3}, {%4,%5,%6,%7}, {%8,%9}, {%0,%1,%2,%3};"
        : "+f"(c[0]), "+f"(c[1]), "+f"(c[2]), "+f"(c[3])
        : "r"(a[0]), "r"(a[1]), "r"(a[2]), "r"(a[3]), "r"(b[0]), "r"(b[1]));
}
__device__ __forceinline__ void ldsm4(uint32_t* r, uint32_t addr) {
    asm volatile("ldmatrix.sync.aligned.m8n8.x4.shared.b16 {%0,%1,%2,%3}, [%4];"
        : "=r"(r[0]), "=r"(r[1]), "=r"(r[2]), "=r"(r[3]) : "r"(addr));
}
__device__ __forceinline__ void ldsm4t(uint32_t* r, uint32_t addr) {
    asm volatile("ldmatrix.sync.aligned.m8n8.x4.trans.shared.b16 {%0,%1,%2,%3}, [%4];"
        : "=r"(r[0]), "=r"(r[1]), "=r"(r[2]), "=r"(r[3]) : "r"(addr));
}
#define CPA16(dst_u32, src_ptr) \
    asm volatile("cp.async.cg.shared.global [%0], [%1], 16;" :: "r"(dst_u32), "l"(src_ptr))
#define CPA_COMMIT() asm volatile("cp.async.commit_group;" ::: "memory")
#define CPA_WAIT(n)  asm volatile("cp.async.wait_group %0;" :: "n"(n) : "memory")

__device__ __forceinline__ float ex2f(float x) {
    float r;
    asm("ex2.approx.f32 %0, %1;" : "=f"(r) : "f"(x));
    return r;
}
__device__ __forceinline__ uint32_t ex2h2(uint32_t a) {
    uint32_t r;
    asm("ex2.approx.f16x2 %0, %1;" : "=r"(r) : "r"(a));
    return r;
}
__device__ __forceinline__ uint32_t packh2(float a, float b) {
    __half2 h = __floats2half2_rn(a, b);      // x = a (low), y = b (high)
    return *reinterpret_cast<uint32_t*>(&h);
}
__device__ __forceinline__ void split2(float p0, float p1, uint32_t& hi, uint32_t& lo) {
    bf162 h = __floats2bfloat162_rn(p0, p1);
    bf162 l = __floats2bfloat162_rn(p0 - __bfloat162float(h.x), p1 - __bfloat162float(h.y));
    hi = *reinterpret_cast<uint32_t*>(&h);
    lo = *reinterpret_cast<uint32_t*>(&l);
}
#define L2E 1.4426950408889634f
#define ONESH2 0x3C003C00u                    // fp16 (1.0, 1.0)

// ======================= conversion kernels (fused over q,k,v) =======================
__global__ __launch_bounds__(256) void cvt_x3(const float* __restrict__ q,
                                              const float* __restrict__ k,
                                              const float* __restrict__ v) {
    const int which = blockIdx.y;
    const float* X = (which == 0) ? q : (which == 1) ? k : v;
    bf16* xh = g_xhi + (size_t)which * BSD;
    bf16* xl = g_xlo + (size_t)which * BSD;
    int i = blockIdx.x * 256 + threadIdx.x;
    float4 x = ((const float4*)X)[i];
    bf16 h0 = __float2bfloat16(x.x), h1 = __float2bfloat16(x.y);
    bf16 h2 = __float2bfloat16(x.z), h3 = __float2bfloat16(x.w);
    bf16 l0 = __float2bfloat16(x.x - __bfloat162float(h0));
    bf16 l1 = __float2bfloat16(x.y - __bfloat162float(h1));
    bf16 l2 = __float2bfloat16(x.z - __bfloat162float(h2));
    bf16 l3 = __float2bfloat16(x.w - __bfloat162float(h3));
    bf162* ph = (bf162*)xh;
    bf162* pl = (bf162*)xl;
    ph[2*i]   = __halves2bfloat162(h0, h1);
    ph[2*i+1] = __halves2bfloat162(h2, h3);
    pl[2*i]   = __halves2bfloat162(l0, l1);
    pl[2*i+1] = __halves2bfloat162(l2, l3);
}
__global__ __launch_bounds__(256) void cvt_w3(const float* __restrict__ Wq,
                                              const float* __restrict__ Wk,
                                              const float* __restrict__ Wv) {
    const int which = blockIdx.y;
    const float* W = (which == 0) ? Wq : (which == 1) ? Wk : Wv;
    bf16* wh = g_whi + (size_t)which * (NN * DD);
    bf16* wl = g_wlo + (size_t)which * (NN * DD);
    int idx = blockIdx.x * 256 + threadIdx.x;
    float4 wv = ((const float4*)W)[idx];
    int a4 = idx & 15;
    int d  = (idx >> 4) & 1023;
    int h  = idx >> 14;
    int nb = h * AA + a4 * 4;
    float vals[4] = {wv.x, wv.y, wv.z, wv.w};
    #pragma unroll
    for (int j = 0; j < 4; j++) {
        bf16 hi = __float2bfloat16(vals[j]);
        bf16 lo = __float2bfloat16(vals[j] - __bfloat162float(hi));
        size_t o = (size_t)(nb + j) * DD + d;
        wh[o] = hi;
        wl[o] = lo;
    }
}

// ======================= projection GEMM =======================
// block tile 128x128, 128 threads, warps 2(m) x 2(n), warp tile 64x64.
#define KC 32
#define XP 40
#define PSTG_H (4*128*XP)
#define PSTG_B (PSTG_H*2)                      // 40960 bytes
#define PROJ_SMEM (2*PSTG_B)                   // 81920

__global__ __launch_bounds__(128, 2) void proj_mma(const float* __restrict__ bq,
                                                   const float* __restrict__ bk,
                                                   const float* __restrict__ bv) {
    const int which = blockIdx.z;
    const float* bias = (which == 0) ? bq : (which == 1) ? bk : bv;
    const bf16* Xh = g_xhi + (size_t)which * BSD;
    const bf16* Xl = g_xlo + (size_t)which * BSD;
    const bf16* Wh = g_whi + (size_t)which * (NN * DD);
    const bf16* Wl = g_wlo + (size_t)which * (NN * DD);
    extern __shared__ bf16 sm[];
    const int t = threadIdx.x, lane = t & 31, wid = t >> 5;
    const int wm = wid & 1, wn = wid >> 1;
    const int r0 = blockIdx.x * 128, n0 = blockIdx.y * 128;
    const uint32_t sbase = smem_u32(sm);

    float c[4][8][4];
    #pragma unroll
    for (int mt = 0; mt < 4; mt++)
        #pragma unroll
        for (int nt = 0; nt < 8; nt++)
            #pragma unroll
            for (int i = 0; i < 4; i++) c[mt][nt][i] = 0.0f;

    // 16 cp.async of 16B per thread per chunk; arr = i>>2 constant per i
#define PROJ_ISSUE(kc_) do {                                                       \
    int k0_ = (kc_) * KC;                                                          \
    uint32_t stg_ = sbase + ((kc_) & 1) * PSTG_B;                                  \
    _Pragma("unroll")                                                              \
    for (int i = 0; i < 16; i++) {                                                 \
        int row = (i & 3) * 32 + (t >> 2); int cq = t & 3;                         \
        const bf16* src;                                                           \
        if      ((i >> 2) == 0) src = Xh + (size_t)(r0 + row) * DD + k0_ + cq * 8; \
        else if ((i >> 2) == 1) src = Xl + (size_t)(r0 + row) * DD + k0_ + cq * 8; \
        else if ((i >> 2) == 2) src = Wh + (size_t)(n0 + row) * DD + k0_ + cq * 8; \
        else                    src = Wl + (size_t)(n0 + row) * DD + k0_ + cq * 8; \
        uint32_t dst = stg_ + ((i >> 2) * (128 * XP) + row * XP + cq * 8) * 2;     \
        CPA16(dst, src);                                                           \
    } } while (0)

    PROJ_ISSUE(0);
    CPA_COMMIT();
    #pragma unroll 1
    for (int kc = 0; kc < DD / KC; kc++) {
        if (kc + 1 < DD / KC) {
            PROJ_ISSUE(kc + 1);
            CPA_COMMIT();
            CPA_WAIT(1);
        } else {
            CPA_WAIT(0);
        }
        __syncthreads();

        const uint32_t stage = sbase + (kc & 1) * PSTG_B;
        #pragma unroll
        for (int ka = 0; ka < 2; ka++) {
            const int kk = ka * 16;
            uint32_t xh[4][4], xl[4][4];
            #pragma unroll
            for (int mt = 0; mt < 4; mt++) {
                uint32_t addr = stage +
                    ((wm * 64 + mt * 16 + (lane & 15)) * XP + kk + (lane >> 4) * 8) * 2;
                ldsm4(xh[mt], addr);
                ldsm4(xl[mt], addr + 128 * XP * 2);
            }
            #pragma unroll
            for (int jp = 0; jp < 4; jp++) {
                uint32_t wh[4], wl[4];
                int brow = wn * 64 + jp * 16 + (lane & 7) + ((lane & 16) ? 8 : 0);
                uint32_t baddr = stage + (2 * 128 * XP) * 2 +
                    (brow * XP + kk + ((lane >> 3) & 1) * 8) * 2;
                ldsm4(wh, baddr);
                ldsm4(wl, baddr + 128 * XP * 2);
                #pragma unroll
                for (int mt = 0; mt < 4; mt++) {
                    mma16816(c[mt][2*jp],   xh[mt], &wh[0]);
                    mma16816(c[mt][2*jp],   xh[mt], &wl[0]);
                    mma16816(c[mt][2*jp],   xl[mt], &wh[0]);
                    mma16816(c[mt][2*jp+1], xh[mt], &wh[2]);
                    mma16816(c[mt][2*jp+1], xh[mt], &wl[2]);
                    mma16816(c[mt][2*jp+1], xl[mt], &wh[2]);
                }
            }
        }
        __syncthreads();
    }

    // epilogue
    const int g = lane >> 2, l = lane & 3;
    #pragma unroll
    for (int mt = 0; mt < 4; mt++) {
        int row = r0 + wm * 64 + mt * 16 + g;
        int b = row >> 11, s = row & (SS - 1);
        #pragma unroll
        for (int nt = 0; nt < 8; nt++) {
            int n = n0 + wn * 64 + nt * 8 + l * 2;
            int h = n >> 6, a = n & 63;
            size_t off = ((size_t)(b * HH + h) * SS + s) * AA + a;
            float bv0 = bias[n], bv1 = bias[n + 1];
            float p0 = c[mt][nt][0] + bv0, p1 = c[mt][nt][1] + bv1;
            float p2 = c[mt][nt][2] + bv0, p3 = c[mt][nt][3] + bv1;
            if (which == 2) {
                *(uint32_t*)(g_vh2 + off)          = packh2(p0, p1);
                *(uint32_t*)(g_vh2 + off + 8 * AA) = packh2(p2, p3);
            } else {
                bf16 *outhi = (which == 0) ? g_qhi : g_khi;
                bf16 *outlo = (which == 0) ? g_qlo : g_klo;
                uint32_t hi, lo;
                split2(p0, p1, hi, lo);
                *(uint32_t*)(outhi + off) = hi;
                *(uint32_t*)(outlo + off) = lo;
                split2(p2, p3, hi, lo);
                *(uint32_t*)(outhi + off + 8 * AA) = hi;
                *(uint32_t*)(outlo + off + 8 * AA) = lo;
            }
        }
    }
}

// ======================= flash attention =======================
// S: bf16 3-term split. P: fp16 via ex2.approx.f16x2. PV: fp16 single term.
// Row sums via all-ones B-frag MMA (consistent with fp16 P).
#define QP 72
#define ASTG_H (3*64*QP)                       // Khi, Klo, V
#define ASTG_B (ASTG_H*2)                      // 27648 bytes
#define OFF_QL (128*QP*2)
#define OFF_ST (256*QP*2)                      // 36864
#define ATTN_SMEM (OFF_ST + 2*ASTG_B)          // 92160 bytes

__global__ __launch_bounds__(256, 2) void attn_mma(float* __restrict__ out) {
    extern __shared__ bf16 smh[];
    bf16* Qh = smh;
    bf16* Ql = Qh + 128 * QP;

    const int bh = blockIdx.y, q0 = blockIdx.x * 128;
    const int t = threadIdx.x, lane = t & 31, wid = t >> 5;
    const int m0w = wid * 16;
    const size_t bhoff = (size_t)bh * SS * AA;
    const uint32_t sb = smem_u32(smh);

#define ATTN_ISSUE(kt_) do {                                                      \
    const size_t toff_ = bhoff + (size_t)(kt_) * 64 * AA;                         \
    uint32_t stg_ = sb + OFF_ST + ((kt_) & 1) * ASTG_B;                           \
    _Pragma("unroll")                                                             \
    for (int i = 0; i < 2; i++) {                                                 \
        int idx = t + i * 256; int row = idx >> 3, cq = idx & 7;                  \
        uint32_t so = stg_ + (row * QP + cq * 8) * 2;                             \
        size_t go = toff_ + row * AA + cq * 8;                                    \
        CPA16(so,              g_khi + go);                                       \
        CPA16(so + 64*QP*2,    g_klo + go);                                       \
        CPA16(so + 128*QP*2,   g_vh2 + go);                                       \
    } } while (0)

    // load Q hi/lo
    {
        const bf16* Qghi = g_qhi + bhoff + (size_t)q0 * AA;
        const bf16* Qglo = g_qlo + bhoff + (size_t)q0 * AA;
        #pragma unroll
        for (int i = 0; i < 4; i++) {
            int idx = t + i * 256;
            int row = idx >> 3, cq = idx & 7;
            *(uint4*)(Qh + row * QP + cq * 8) = *(const uint4*)(Qghi + row * AA + cq * 8);
            *(uint4*)(Ql + row * QP + cq * 8) = *(const uint4*)(Qglo + row * AA + cq * 8);
        }
    }

    ATTN_ISSUE(0);
    CPA_COMMIT();

    float o[8][4];
    float ls[4] = {0.0f, 0.0f, 0.0f, 0.0f};   // row-sum accumulators (ones-MMA)
    #pragma unroll
    for (int j = 0; j < 8; j++)
        #pragma unroll
        for (int i = 0; i < 4; i++) o[j][i] = 0.0f;
    float mi0 = -INFINITY, mi1 = -INFINITY;
    const uint32_t onesb[2] = {ONESH2, ONESH2};

    #pragma unroll 1
    for (int kt = 0; kt < SS / 64; kt++) {
        if (kt + 1 < SS / 64) {
            ATTN_ISSUE(kt + 1);
            CPA_COMMIT();
            CPA_WAIT(1);
        } else {
            CPA_WAIT(0);
        }
        __syncthreads();
        const uint32_t stg = sb + OFF_ST + (kt & 1) * ASTG_B;

        // ---- S = Q K^T, bf16 3-term split
        float s[8][4];
        #pragma unroll
        for (int j = 0; j < 8; j++)
            #pragma unroll
            for (int i = 0; i < 4; i++) s[j][i] = 0.0f;

        #pragma unroll
        for (int ka = 0; ka < 4; ka++) {
            const int a0 = ka * 16;
            uint32_t qh[4], ql[4];
            uint32_t qaddr = sb + ((m0w + (lane & 15)) * QP + a0 + (lane >> 4) * 8) * 2;
            ldsm4(qh, qaddr);
            ldsm4(ql, qaddr + OFF_QL);
            #pragma unroll
            for (int jp = 0; jp < 4; jp++) {
                uint32_t kh4[4], kl4[4];
                int krow = jp * 16 + (lane & 7) + ((lane & 16) ? 8 : 0);
                uint32_t kaddr = stg + (krow * QP + a0 + ((lane >> 3) & 1) * 8) * 2;
                ldsm4(kh4, kaddr);
                ldsm4(kl4, kaddr + 64 * QP * 2);
                mma16816(s[2*jp],   qh, &kh4[0]);
                mma16816(s[2*jp],   qh, &kl4[0]);
                mma16816(s[2*jp],   ql, &kh4[0]);
                mma16816(s[2*jp+1], qh, &kh4[2]);
                mma16816(s[2*jp+1], qh, &kl4[2]);
                mma16816(s[2*jp+1], ql, &kh4[2]);
            }
        }

        // ---- online softmax: max reduce, fp16 P via ex2.f16x2
        float tm0 = -INFINITY, tm1 = -INFINITY;
        #pragma unroll
        for (int j = 0; j < 8; j++) {
            tm0 = fmaxf(tm0, fmaxf(s[j][0], s[j][1]));
            tm1 = fmaxf(tm1, fmaxf(s[j][2], s[j][3]));
        }
        tm0 = fmaxf(tm0, __shfl_xor_sync(0xffffffffu, tm0, 1));
        tm0 = fmaxf(tm0, __shfl_xor_sync(0xffffffffu, tm0, 2));
        tm1 = fmaxf(tm1, __shfl_xor_sync(0xffffffffu, tm1, 1));
        tm1 = fmaxf(tm1, __shfl_xor_sync(0xffffffffu, tm1, 2));
        float mn0 = fmaxf(mi0, tm0), mn1 = fmaxf(mi1, tm1);
        float corr0 = ex2f((mi0 - mn0) * L2E);
        float corr1 = ex2f((mi1 - mn1) * L2E);
        mi0 = mn0; mi1 = mn1;
        const float b0 = -mn0 * L2E, b1 = -mn1 * L2E;
        uint32_t ps[8][2];
        #pragma unroll
        for (int j = 0; j < 8; j++) {
            ps[j][0] = ex2h2(packh2(fmaf(s[j][0], L2E, b0), fmaf(s[j][1], L2E, b0)));
            ps[j][1] = ex2h2(packh2(fmaf(s[j][2], L2E, b1), fmaf(s[j][3], L2E, b1)));
        }
        // rescale running O and row-sum accumulators
        #pragma unroll
        for (int j = 0; j < 8; j++) {
            o[j][0] *= corr0; o[j][1] *= corr0;
            o[j][2] *= corr1; o[j][3] *= corr1;
        }
        ls[0] *= corr0; ls[1] *= corr0; ls[2] *= corr1; ls[3] *= corr1;

        // ---- O += P V (fp16), row sums via ones-MMA
        #pragma unroll
        for (int kc = 0; kc < 4; kc++) {
            uint32_t pa[4];
            pa[0] = ps[2*kc][0];
            pa[1] = ps[2*kc][1];
            pa[2] = ps[2*kc+1][0];
            pa[3] = ps[2*kc+1][1];
            mma16816h(ls, pa, onesb);
            #pragma unroll
            for (int jp = 0; jp < 4; jp++) {
                uint32_t vh4[4];
                int vrow = kc * 16 + (lane & 7) + ((lane >> 3) & 1) * 8;
                uint32_t vaddr = stg + 128 * QP * 2 +
                    (vrow * QP + jp * 16 + ((lane & 16) ? 8 : 0)) * 2;
                ldsm4t(vh4, vaddr);
                mma16816h(o[2*jp],   pa, &vh4[0]);
                mma16816h(o[2*jp+1], pa, &vh4[2]);
            }
        }
        __syncthreads();
    }

    // ---- epilogue: normalize by ones-MMA row sums
    const float inv0 = 1.0f / ls[0], inv1 = 1.0f / ls[2];
    const int g = lane >> 2, l = lane & 3;
    const int b = bh >> 4, h = bh & 15;
    const int row0 = q0 + m0w + g;
    float* outp = out + ((size_t)b * SS + row0) * NN + h * AA;
    #pragma unroll
    for (int j = 0; j < 8; j++) {
        float2 w0 = make_float2(o[j][0] * inv0, o[j][1] * inv0);
        float2 w1 = make_float2(o[j][2] * inv1, o[j][3] * inv1);
        *(float2*)(outp + j * 8 + l * 2) = w0;
        *(float2*)(outp + (size_t)8 * NN + j * 8 + l * 2) = w1;
    }
}

extern "C" void kernel_launch(void* const* d_in, const int* in_sizes, int n_in,
                              void* d_out, int out_size) {
    (void)in_sizes; (void)n_in; (void)out_size;
    const float* q  = (const float*)d_in[0];
    const float* k  = (const float*)d_in[1];
    const float* v  = (const float*)d_in[2];
    const float* Wq = (const float*)d_in[3];
    const float* bq = (const float*)d_in[4];
    const float* Wk = (const float*)d_in[5];
    const float* bk = (const float*)d_in[6];
    const float* Wv = (const float*)d_in[7];
    const float* bv = (const float*)d_in[8];
    float* out = (float*)d_out;

    cudaFuncSetAttribute(proj_mma, cudaFuncAttributeMaxDynamicSharedMemorySize, PROJ_SMEM);
    cudaFuncSetAttribute(attn_mma, cudaFuncAttributeMaxDynamicSharedMemorySize, ATTN_SMEM);

    cvt_x3<<<dim3(8192, 3), 256>>>(q, k, v);
    cvt_w3<<<dim3(1024, 3), 256>>>(Wq, Wk, Wv);
    proj_mma<<<dim3(64, 8, 3), 128, PROJ_SMEM>>>(bq, bk, bv);

    dim3 ag(SS / 128, BB * HH);
    attn_mma<<<ag, 256, ATTN_SMEM>>>(out);
}

// round 8
// speedup vs baseline: 3.6136x; 1.0120x over previous
#include <cuda_runtime.h>
#include <cuda_bf16.h>
#include <cuda_fp16.h>
#include <math.h>
#include <stdint.h>

#define BB 4
#define SS 2048
#define DD 1024
#define HH 16
#define AA 64
#define NN (HH*AA)   // 1024
#define BSD (BB*SS*DD)

typedef __nv_bfloat16 bf16;
typedef __nv_bfloat162 bf162;

// ---- scratch ----
__device__ bf16 g_qhi[BB*HH*SS*AA];
__device__ bf16 g_qlo[BB*HH*SS*AA];
__device__ bf16 g_khi[BB*HH*SS*AA];
__device__ bf16 g_klo[BB*HH*SS*AA];
__device__ __half g_vh2[BB*HH*SS*AA];        // V single fp16
__device__ bf16 g_xhi[3*BSD];
__device__ bf16 g_xlo[3*BSD];
__device__ bf16 g_whi[3*NN*DD];
__device__ bf16 g_wlo[3*NN*DD];

// ======================= helpers =======================
__device__ __forceinline__ uint32_t smem_u32(const void* p) {
    uint32_t a;
    asm("{ .reg .u64 t; cvta.to.shared.u64 t, %1; cvt.u32.u64 %0, t; }" : "=r"(a) : "l"(p));
    return a;
}
__device__ __forceinline__ void mma16816(float* c, const uint32_t* a, const uint32_t* b) {
    asm volatile(
        "mma.sync.aligned.m16n8k16.row.col.f32.bf16.bf16.f32 "
        "{%0,%1,%2,%3}, {%4,%5,%6,%7}, {%8,%9}, {%0,%1,%2,%3};"
        : "+f"(c[0]), "+f"(c[1]), "+f"(c[2]), "+f"(c[3])
        : "r"(a[0]), "r"(a[1]), "r"(a[2]), "r"(a[3]), "r"(b[0]), "r"(b[1]));
}
__device__ __forceinline__ void mma16816h(float* c, const uint32_t* a, const uint32_t* b) {
    asm volatile(
        "mma.sync.aligned.m16n8k16.row.col.f32.f16.f16.f32 "
        "{%0,%1,%2,%3}, {%4,%5,%6,%7}, {%8,%9}, {%0,%1,%2,%3};"
        : "+f"(c[0]), "+f"(c[1]), "+f"(c[2]), "+f"(c[3])
        : "r"(a[0]), "r"(a[1]), "r"(a[2]), "r"(a[3]), "r"(b[0]), "r"(b[1]));
}
__device__ __forceinline__ void ldsm4(uint32_t* r, uint32_t addr) {
    asm volatile("ldmatrix.sync.aligned.m8n8.x4.shared.b16 {%0,%1,%2,%3}, [%4];"
        : "=r"(r[0]), "=r"(r[1]), "=r"(r[2]), "=r"(r[3]) : "r"(addr));
}
__device__ __forceinline__ void ldsm4t(uint32_t* r, uint32_t addr) {
    asm volatile("ldmatrix.sync.aligned.m8n8.x4.trans.shared.b16 {%0,%1,%2,%3}, [%4];"
        : "=r"(r[0]), "=r"(r[1]), "=r"(r[2]), "=r"(r[3]) : "r"(addr));
}
#define CPA16(dst_u32, src_ptr) \
    asm volatile("cp.async.cg.shared.global [%0], [%1], 16;" :: "r"(dst_u32), "l"(src_ptr))
#define CPA_COMMIT() asm volatile("cp.async.commit_group;" ::: "memory")
#define CPA_WAIT(n)  asm volatile("cp.async.wait_group %0;" :: "n"(n) : "memory")

__device__ __forceinline__ float ex2f(float x) {
    float r;
    asm("ex2.approx.f32 %0, %1;" : "=f"(r) : "f"(x));
    return r;
}
__device__ __forceinline__ uint32_t ex2h2(uint32_t a) {
    uint32_t r;
    asm("ex2.approx.f16x2 %0, %1;" : "=r"(r) : "r"(a));
    return r;
}
__device__ __forceinline__ uint32_t packh2(float a, float b) {
    __half2 h = __floats2half2_rn(a, b);      // x = a (low), y = b (high)
    return *reinterpret_cast<uint32_t*>(&h);
}
__device__ __forceinline__ uint32_t packbf2(float a, float b) {
    bf162 h = __floats2bfloat162_rn(a, b);
    return *reinterpret_cast<uint32_t*>(&h);
}
__device__ __forceinline__ void split2(float p0, float p1, uint32_t& hi, uint32_t& lo) {
    bf162 h = __floats2bfloat162_rn(p0, p1);
    bf162 l = __floats2bfloat162_rn(p0 - __bfloat162float(h.x), p1 - __bfloat162float(h.y));
    hi = *reinterpret_cast<uint32_t*>(&h);
    lo = *reinterpret_cast<uint32_t*>(&l);
}
#define L2E 1.4426950408889634f
#define ONESH2 0x3C003C00u                    // fp16 (1.0, 1.0)

// ======================= conversion kernels (fused over q,k,v) =======================
// 8 floats per thread -> one uint4 hi + one uint4 lo (16B stores)
__global__ __launch_bounds__(256) void cvt_x3(const float* __restrict__ q,
                                              const float* __restrict__ k,
                                              const float* __restrict__ v) {
    const int which = blockIdx.y;
    const float* X = (which == 0) ? q : (which == 1) ? k : v;
    bf16* xh = g_xhi + (size_t)which * BSD;
    bf16* xl = g_xlo + (size_t)which * BSD;
    int i = blockIdx.x * 256 + threadIdx.x;    // 0..BSD/8-1
    float4 a = ((const float4*)X)[2*i];
    float4 b = ((const float4*)X)[2*i+1];
    float f[8] = {a.x, a.y, a.z, a.w, b.x, b.y, b.z, b.w};
    uint32_t hw[4], lw[4];
    #pragma unroll
    for (int j = 0; j < 4; j++) {
        bf16 h0 = __float2bfloat16(f[2*j]);
        bf16 h1 = __float2bfloat16(f[2*j+1]);
        float l0 = f[2*j]   - __bfloat162float(h0);
        float l1 = f[2*j+1] - __bfloat162float(h1);
        bf162 hh = __halves2bfloat162(h0, h1);
        hw[j] = *reinterpret_cast<uint32_t*>(&hh);
        lw[j] = packbf2(l0, l1);
    }
    ((uint4*)xh)[i] = make_uint4(hw[0], hw[1], hw[2], hw[3]);
    ((uint4*)xl)[i] = make_uint4(lw[0], lw[1], lw[2], lw[3]);
}
__global__ __launch_bounds__(256) void cvt_w3(const float* __restrict__ Wq,
                                              const float* __restrict__ Wk,
                                              const float* __restrict__ Wv) {
    const int which = blockIdx.y;
    const float* W = (which == 0) ? Wq : (which == 1) ? Wk : Wv;
    bf16* wh = g_whi + (size_t)which * (NN * DD);
    bf16* wl = g_wlo + (size_t)which * (NN * DD);
    int idx = blockIdx.x * 256 + threadIdx.x;
    float4 wv = ((const float4*)W)[idx];
    int a4 = idx & 15;
    int d  = (idx >> 4) & 1023;
    int h  = idx >> 14;
    int nb = h * AA + a4 * 4;
    float vals[4] = {wv.x, wv.y, wv.z, wv.w};
    #pragma unroll
    for (int j = 0; j < 4; j++) {
        bf16 hi = __float2bfloat16(vals[j]);
        bf16 lo = __float2bfloat16(vals[j] - __bfloat162float(hi));
        size_t o = (size_t)(nb + j) * DD + d;
        wh[o] = hi;
        wl[o] = lo;
    }
}

// ======================= projection GEMM =======================
// block tile 128x128, 256 threads, warps 4(m) x 2(n), warp tile 32x64.
#define KC 32
#define XP 40
#define PSTG_H (4*128*XP)
#define PSTG_B (PSTG_H*2)                      // 40960 bytes
#define PROJ_SMEM (2*PSTG_B)                   // 81920

__global__ __launch_bounds__(256, 2) void proj_mma(const float* __restrict__ bq,
                                                   const float* __restrict__ bk,
                                                   const float* __restrict__ bv) {
    const int which = blockIdx.z;
    const float* bias = (which == 0) ? bq : (which == 1) ? bk : bv;
    const bf16* Xh = g_xhi + (size_t)which * BSD;
    const bf16* Xl = g_xlo + (size_t)which * BSD;
    const bf16* Wh = g_whi + (size_t)which * (NN * DD);
    const bf16* Wl = g_wlo + (size_t)which * (NN * DD);
    extern __shared__ bf16 sm[];
    const int t = threadIdx.x, lane = t & 31, wid = t >> 5;
    const int wm = wid & 3, wn = wid >> 2;
    const int r0 = blockIdx.x * 128, n0 = blockIdx.y * 128;
    const uint32_t sbase = smem_u32(sm);

    float c[2][8][4];
    #pragma unroll
    for (int mt = 0; mt < 2; mt++)
        #pragma unroll
        for (int nt = 0; nt < 8; nt++)
            #pragma unroll
            for (int i = 0; i < 4; i++) c[mt][nt][i] = 0.0f;

    // 8 cp.async of 16B per thread per chunk (256 threads)
#define PROJ_ISSUE(kc_) do {                                                       \
    int k0_ = (kc_) * KC;                                                          \
    uint32_t stg_ = sbase + ((kc_) & 1) * PSTG_B;                                  \
    _Pragma("unroll")                                                              \
    for (int i = 0; i < 8; i++) {                                                  \
        int rem = ((i & 1) << 8) + t; int row = rem >> 2, cq = rem & 3;            \
        const bf16* src;                                                           \
        if      ((i >> 1) == 0) src = Xh + (size_t)(r0 + row) * DD + k0_ + cq * 8; \
        else if ((i >> 1) == 1) src = Xl + (size_t)(r0 + row) * DD + k0_ + cq * 8; \
        else if ((i >> 1) == 2) src = Wh + (size_t)(n0 + row) * DD + k0_ + cq * 8; \
        else                    src = Wl + (size_t)(n0 + row) * DD + k0_ + cq * 8; \
        uint32_t dst = stg_ + ((i >> 1) * (128 * XP) + row * XP + cq * 8) * 2;     \
        CPA16(dst, src);                                                           \
    } } while (0)

    PROJ_ISSUE(0);
    CPA_COMMIT();
    #pragma unroll 1
    for (int kc = 0; kc < DD / KC; kc++) {
        if (kc + 1 < DD / KC) {
            PROJ_ISSUE(kc + 1);
            CPA_COMMIT();
            CPA_WAIT(1);
        } else {
            CPA_WAIT(0);
        }
        __syncthreads();

        const uint32_t stage = sbase + (kc & 1) * PSTG_B;
        #pragma unroll
        for (int ka = 0; ka < 2; ka++) {
            const int kk = ka * 16;
            uint32_t xh[2][4], xl[2][4];
            #pragma unroll
            for (int mt = 0; mt < 2; mt++) {
                uint32_t addr = stage +
                    ((wm * 32 + mt * 16 + (lane & 15)) * XP + kk + (lane >> 4) * 8) * 2;
                ldsm4(xh[mt], addr);
                ldsm4(xl[mt], addr + 128 * XP * 2);
            }
            #pragma unroll
            for (int jp = 0; jp < 4; jp++) {
                uint32_t wh[4], wl[4];
                int brow = wn * 64 + jp * 16 + (lane & 7) + ((lane & 16) ? 8 : 0);
                uint32_t baddr = stage + (2 * 128 * XP) * 2 +
                    (brow * XP + kk + ((lane >> 3) & 1) * 8) * 2;
                ldsm4(wh, baddr);
                ldsm4(wl, baddr + 128 * XP * 2);
                #pragma unroll
                for (int mt = 0; mt < 2; mt++) {
                    mma16816(c[mt][2*jp],   xh[mt], &wh[0]);
                    mma16816(c[mt][2*jp],   xh[mt], &wl[0]);
                    mma16816(c[mt][2*jp],   xl[mt], &wh[0]);
                    mma16816(c[mt][2*jp+1], xh[mt], &wh[2]);
                    mma16816(c[mt][2*jp+1], xh[mt], &wl[2]);
                    mma16816(c[mt][2*jp+1], xl[mt], &wh[2]);
                }
            }
        }
        __syncthreads();
    }

    // epilogue
    const int g = lane >> 2, l = lane & 3;
    #pragma unroll
    for (int mt = 0; mt < 2; mt++) {
        int row = r0 + wm * 32 + mt * 16 + g;
        int b = row >> 11, s = row & (SS - 1);
        #pragma unroll
        for (int nt = 0; nt < 8; nt++) {
            int n = n0 + wn * 64 + nt * 8 + l * 2;
            int h = n >> 6, a = n & 63;
            size_t off = ((size_t)(b * HH + h) * SS + s) * AA + a;
            float bv0 = bias[n], bv1 = bias[n + 1];
            float p0 = c[mt][nt][0] + bv0, p1 = c[mt][nt][1] + bv1;
            float p2 = c[mt][nt][2] + bv0, p3 = c[mt][nt][3] + bv1;
            if (which == 2) {
                *(uint32_t*)(g_vh2 + off)          = packh2(p0, p1);
                *(uint32_t*)(g_vh2 + off + 8 * AA) = packh2(p2, p3);
            } else {
                bf16 *outhi = (which == 0) ? g_qhi : g_khi;
                bf16 *outlo = (which == 0) ? g_qlo : g_klo;
                uint32_t hi, lo;
                split2(p0, p1, hi, lo);
                *(uint32_t*)(outhi + off) = hi;
                *(uint32_t*)(outlo + off) = lo;
                split2(p2, p3, hi, lo);
                *(uint32_t*)(outhi + off + 8 * AA) = hi;
                *(uint32_t*)(outlo + off + 8 * AA) = lo;
            }
        }
    }
}

// ======================= flash attention =======================
// S: bf16 3-term split. P: fp16 via ex2.approx.f16x2. PV: fp16 single term.
// Row sums via all-ones B-frag MMA. Skip O-rescale when max unchanged.
#define QP 72
#define ASTG_H (3*64*QP)                       // Khi, Klo, V
#define ASTG_B (ASTG_H*2)                      // 27648 bytes
#define OFF_QL (128*QP*2)
#define OFF_ST (256*QP*2)                      // 36864
#define ATTN_SMEM (OFF_ST + 2*ASTG_B)          // 92160 bytes

__global__ __launch_bounds__(256, 2) void attn_mma(float* __restrict__ out) {
    extern __shared__ bf16 smh[];
    bf16* Qh = smh;
    bf16* Ql = Qh + 128 * QP;

    const int bh = blockIdx.y, q0 = blockIdx.x * 128;
    const int t = threadIdx.x, lane = t & 31, wid = t >> 5;
    const int m0w = wid * 16;
    const size_t bhoff = (size_t)bh * SS * AA;
    const uint32_t sb = smem_u32(smh);

#define ATTN_ISSUE(kt_) do {                                                      \
    const size_t toff_ = bhoff + (size_t)(kt_) * 64 * AA;                         \
    uint32_t stg_ = sb + OFF_ST + ((kt_) & 1) * ASTG_B;                           \
    _Pragma("unroll")                                                             \
    for (int i = 0; i < 2; i++) {                                                 \
        int idx = t + i * 256; int row = idx >> 3, cq = idx & 7;                  \
        uint32_t so = stg_ + (row * QP + cq * 8) * 2;                             \
        size_t go = toff_ + row * AA + cq * 8;                                    \
        CPA16(so,              g_khi + go);                                       \
        CPA16(so + 64*QP*2,    g_klo + go);                                       \
        CPA16(so + 128*QP*2,   g_vh2 + go);                                       \
    } } while (0)

    // load Q hi/lo
    {
        const bf16* Qghi = g_qhi + bhoff + (size_t)q0 * AA;
        const bf16* Qglo = g_qlo + bhoff + (size_t)q0 * AA;
        #pragma unroll
        for (int i = 0; i < 4; i++) {
            int idx = t + i * 256;
            int row = idx >> 3, cq = idx & 7;
            *(uint4*)(Qh + row * QP + cq * 8) = *(const uint4*)(Qghi + row * AA + cq * 8);
            *(uint4*)(Ql + row * QP + cq * 8) = *(const uint4*)(Qglo + row * AA + cq * 8);
        }
    }

    ATTN_ISSUE(0);
    CPA_COMMIT();

    float o[8][4];
    float ls[4] = {0.0f, 0.0f, 0.0f, 0.0f};
    #pragma unroll
    for (int j = 0; j < 8; j++)
        #pragma unroll
        for (int i = 0; i < 4; i++) o[j][i] = 0.0f;
    float mi0 = -INFINITY, mi1 = -INFINITY;
    const uint32_t onesb[2] = {ONESH2, ONESH2};

    #pragma unroll 1
    for (int kt = 0; kt < SS / 64; kt++) {
        if (kt + 1 < SS / 64) {
            ATTN_ISSUE(kt + 1);
            CPA_COMMIT();
            CPA_WAIT(1);
        } else {
            CPA_WAIT(0);
        }
        __syncthreads();
        const uint32_t stg = sb + OFF_ST + (kt & 1) * ASTG_B;

        // ---- S = Q K^T, bf16 3-term split
        float s[8][4];
        #pragma unroll
        for (int j = 0; j < 8; j++)
            #pragma unroll
            for (int i = 0; i < 4; i++) s[j][i] = 0.0f;

        #pragma unroll
        for (int ka = 0; ka < 4; ka++) {
            const int a0 = ka * 16;
            uint32_t qh[4], ql[4];
            uint32_t qaddr = sb + ((m0w + (lane & 15)) * QP + a0 + (lane >> 4) * 8) * 2;
            ldsm4(qh, qaddr);
            ldsm4(ql, qaddr + OFF_QL);
            #pragma unroll
            for (int jp = 0; jp < 4; jp++) {
                uint32_t kh4[4], kl4[4];
                int krow = jp * 16 + (lane & 7) + ((lane & 16) ? 8 : 0);
                uint32_t kaddr = stg + (krow * QP + a0 + ((lane >> 3) & 1) * 8) * 2;
                ldsm4(kh4, kaddr);
                ldsm4(kl4, kaddr + 64 * QP * 2);
                mma16816(s[2*jp],   qh, &kh4[0]);
                mma16816(s[2*jp],   qh, &kl4[0]);
                mma16816(s[2*jp],   ql, &kh4[0]);
                mma16816(s[2*jp+1], qh, &kh4[2]);
                mma16816(s[2*jp+1], qh, &kl4[2]);
                mma16816(s[2*jp+1], ql, &kh4[2]);
            }
        }

        // ---- online softmax
        float tm0 = -INFINITY, tm1 = -INFINITY;
        #pragma unroll
        for (int j = 0; j < 8; j++) {
            tm0 = fmaxf(tm0, fmaxf(s[j][0], s[j][1]));
            tm1 = fmaxf(tm1, fmaxf(s[j][2], s[j][3]));
        }
        tm0 = fmaxf(tm0, __shfl_xor_sync(0xffffffffu, tm0, 1));
        tm0 = fmaxf(tm0, __shfl_xor_sync(0xffffffffu, tm0, 2));
        tm1 = fmaxf(tm1, __shfl_xor_sync(0xffffffffu, tm1, 1));
        tm1 = fmaxf(tm1, __shfl_xor_sync(0xffffffffu, tm1, 2));
        float mn0 = fmaxf(mi0, tm0), mn1 = fmaxf(mi1, tm1);
        // rescale only when the running max moved (rare after early tiles)
        if (tm0 > mi0 || tm1 > mi1) {
            float corr0 = ex2f((mi0 - mn0) * L2E);
            float corr1 = ex2f((mi1 - mn1) * L2E);
            #pragma unroll
            for (int j = 0; j < 8; j++) {
                o[j][0] *= corr0; o[j][1] *= corr0;
                o[j][2] *= corr1; o[j][3] *= corr1;
            }
            ls[0] *= corr0; ls[1] *= corr0; ls[2] *= corr1; ls[3] *= corr1;
            mi0 = mn0; mi1 = mn1;
        }
        const float b0 = -mi0 * L2E, b1 = -mi1 * L2E;
        uint32_t ps[8][2];
        #pragma unroll
        for (int j = 0; j < 8; j++) {
            ps[j][0] = ex2h2(packh2(fmaf(s[j][0], L2E, b0), fmaf(s[j][1], L2E, b0)));
            ps[j][1] = ex2h2(packh2(fmaf(s[j][2], L2E, b1), fmaf(s[j][3], L2E, b1)));
        }

        // ---- O += P V (fp16), row sums via ones-MMA
        #pragma unroll
        for (int kc = 0; kc < 4; kc++) {
            uint32_t pa[4];
            pa[0] = ps[2*kc][0];
            pa[1] = ps[2*kc][1];
            pa[2] = ps[2*kc+1][0];
            pa[3] = ps[2*kc+1][1];
            mma16816h(ls, pa, onesb);
            #pragma unroll
            for (int jp = 0; jp < 4; jp++) {
                uint32_t vh4[4];
                int vrow = kc * 16 + (lane & 7) + ((lane >> 3) & 1) * 8;
                uint32_t vaddr = stg + 128 * QP * 2 +
                    (vrow * QP + jp * 16 + ((lane & 16) ? 8 : 0)) * 2;
                ldsm4t(vh4, vaddr);
                mma16816h(o[2*jp],   pa, &vh4[0]);
                mma16816h(o[2*jp+1], pa, &vh4[2]);
            }
        }
        __syncthreads();
    }

    // ---- epilogue: normalize by ones-MMA row sums
    const float inv0 = 1.0f / ls[0], inv1 = 1.0f / ls[2];
    const int g = lane >> 2, l = lane & 3;
    const int b = bh >> 4, h = bh & 15;
    const int row0 = q0 + m0w + g;
    float* outp = out + ((size_t)b * SS + row0) * NN + h * AA;
    #pragma unroll
    for (int j = 0; j < 8; j++) {
        float2 w0 = make_float2(o[j][0] * inv0, o[j][1] * inv0);
        float2 w1 = make_float2(o[j][2] * inv1, o[j][3] * inv1);
        *(float2*)(outp + j * 8 + l * 2) = w0;
        *(float2*)(outp + (size_t)8 * NN + j * 8 + l * 2) = w1;
    }
}

extern "C" void kernel_launch(void* const* d_in, const int* in_sizes, int n_in,
                              void* d_out, int out_size) {
    (void)in_sizes; (void)n_in; (void)out_size;
    const float* q  = (const float*)d_in[0];
    const float* k  = (const float*)d_in[1];
    const float* v  = (const float*)d_in[2];
    const float* Wq = (const float*)d_in[3];
    const float* bq = (const float*)d_in[4];
    const float* Wk = (const float*)d_in[5];
    const float* bk = (const float*)d_in[6];
    const float* Wv = (const float*)d_in[7];
    const float* bv = (const float*)d_in[8];
    float* out = (float*)d_out;

    cudaFuncSetAttribute(proj_mma, cudaFuncAttributeMaxDynamicSharedMemorySize, PROJ_SMEM);
    cudaFuncSetAttribute(attn_mma, cudaFuncAttributeMaxDynamicSharedMemorySize, ATTN_SMEM);

    cvt_x3<<<dim3(4096, 3), 256>>>(q, k, v);
    cvt_w3<<<dim3(1024, 3), 256>>>(Wq, Wk, Wv);
    proj_mma<<<dim3(64, 8, 3), 256, PROJ_SMEM>>>(bq, bk, bv);

    dim3 ag(SS / 128, BB * HH);
    attn_mma<<<ag, 256, ATTN_SMEM>>>(out);
}